// round 12
// baseline (speedup 1.0000x reference)
#include <cuda_runtime.h>
#include <cuda_bf16.h>
#include <cstdint>
#include <math.h>

#define NSEQ 4096
#define BATCH 2
#define BN (BATCH*NSEQ)
#define FDIM 512
#define DDIM 64
#define MASKVAL (-12800.0f)
#define SCALE_LOG2E (0.125f*1.4426950408889634f)
#define SQ 72   // padded bf16 row stride for mma smem tiles

// ---------------- scratch (device globals; no allocation allowed) ----------------
__device__ float g_Q[(size_t)BN*DDIM];
__device__ float g_K[(size_t)BN*DDIM];
__device__ float g_C[(size_t)BATCH*NSEQ*NSEQ];   // C' = (QK^T/8)*log2e; above-diag of diag tiles = MASKVAL
__device__ float g_ch0[BN];                      // initial charge
__device__ float g_recvT[4][BN];                 // received, per iteration
__device__ float g_rsT[4][BN];                   // row sums, per iteration

__device__ __forceinline__ float sigmoidf_(float x){ return 1.f/(1.f+__expf(-x)); }
__device__ __forceinline__ float ex2_(float x){ float y; asm("ex2.approx.f32 %0, %1;" : "=f"(y) : "f"(x)); return y; }
__device__ __forceinline__ uint32_t smem_u32_(const void* p){
    uint32_t a;
    asm("{ .reg .u64 t; cvta.to.shared.u64 t, %1; cvt.u32.u64 %0, t; }" : "=r"(a) : "l"(p));
    return a;
}
__device__ __forceinline__ void tri_decode_(int kidx, int& ti, int& tj){
    int t = (int)((sqrtf(8.f*(float)kidx + 1.f) - 1.f) * 0.5f);
    while ((t+1)*(t+2)/2 <= kidx) t++;
    while (t*(t+1)/2 > kidx) t--;
    ti = t; tj = kidx - t*(t+1)/2;
}

// ---------------- Q/K projection via mma.sync bf16 hi/lo + in-register RoPE ----------------
#define QK_SMEM_B (27648*2)

__global__ void __launch_bounds__(256) qk_mma_kernel(const float* __restrict__ feat,
                                                     const float* __restrict__ cosb,
                                                     const float* __restrict__ sinb,
                                                     const float* __restrict__ Wq,
                                                     const float* __restrict__ Wk)
{
    extern __shared__ __nv_bfloat16 sm[];
    __nv_bfloat16* Ahi = sm;
    __nv_bfloat16* Alo = sm + 4608;
    int tid = threadIdx.x, lane = tid & 31, w = tid >> 5;
    long rowbase = (long)blockIdx.x*64;
    int isK = w >> 2;
    int wr0 = (w & 3)*16;
    float acc[8][4] = {};

    for (int f0 = 0; f0 < FDIM; f0 += 64){
        __syncthreads();
        for (int i = tid; i < 64*32; i += 256){
            int r = i >> 5, c2 = i & 31;
            float2 v = *(const float2*)&feat[(rowbase + r)*FDIM + f0 + c2*2];
            __nv_bfloat16 hx = __float2bfloat16_rn(v.x), hy = __float2bfloat16_rn(v.y);
            __nv_bfloat16 lx = __float2bfloat16_rn(v.x - __bfloat162float(hx));
            __nv_bfloat16 ly = __float2bfloat16_rn(v.y - __bfloat162float(hy));
            int o = r*SQ + c2*2;
            *(__nv_bfloat162*)&Ahi[o] = __nv_bfloat162(hx, hy);
            *(__nv_bfloat162*)&Alo[o] = __nv_bfloat162(lx, ly);
        }
        for (int i = tid; i < 64*32; i += 256){
            int f = i >> 5, c2 = i & 31;
            float2 q = *(const float2*)&Wq[(f0+f)*DDIM + c2*2];
            float2 k = *(const float2*)&Wk[(f0+f)*DDIM + c2*2];
            int o = f*SQ + c2*2;
            __nv_bfloat16 qhx = __float2bfloat16_rn(q.x), qhy = __float2bfloat16_rn(q.y);
            __nv_bfloat16 khx = __float2bfloat16_rn(k.x), khy = __float2bfloat16_rn(k.y);
            __nv_bfloat16 qlx = __float2bfloat16_rn(q.x - __bfloat162float(qhx));
            __nv_bfloat16 qly = __float2bfloat16_rn(q.y - __bfloat162float(qhy));
            __nv_bfloat16 klx = __float2bfloat16_rn(k.x - __bfloat162float(khx));
            __nv_bfloat16 kly = __float2bfloat16_rn(k.y - __bfloat162float(khy));
            *(__nv_bfloat162*)&sm[ 9216 + o] = __nv_bfloat162(qhx, qhy);
            *(__nv_bfloat162*)&sm[13824 + o] = __nv_bfloat162(qlx, qly);
            *(__nv_bfloat162*)&sm[18432 + o] = __nv_bfloat162(khx, khy);
            *(__nv_bfloat162*)&sm[23040 + o] = __nv_bfloat162(klx, kly);
        }
        __syncthreads();

        uint32_t a_hi = smem_u32_(Ahi), a_lo = smem_u32_(Alo);
        uint32_t b_hi = smem_u32_(sm + (isK ? 18432 : 9216));
        uint32_t b_lo = smem_u32_(sm + (isK ? 23040 : 13824));
        #pragma unroll
        for (int combo = 0; combo < 3; combo++){
            uint32_t abase = (combo == 2) ? a_lo : a_hi;
            uint32_t bbase = (combo == 1) ? b_lo : b_hi;
            #pragma unroll
            for (int k0 = 0; k0 < 64; k0 += 16){
                uint32_t a[4];
                uint32_t aaddr = abase + (uint32_t)(((wr0 + (lane & 15))*SQ + k0 + (lane >> 4)*8)*2);
                asm volatile("ldmatrix.sync.aligned.m8n8.x4.shared.b16 {%0,%1,%2,%3}, [%4];"
                    : "=r"(a[0]), "=r"(a[1]), "=r"(a[2]), "=r"(a[3]) : "r"(aaddr));
                #pragma unroll
                for (int j = 0; j < 8; j++){
                    uint32_t b0, b1;
                    uint32_t baddr = bbase + (uint32_t)(((k0 + (lane & 15))*SQ + j*8)*2);
                    asm volatile("ldmatrix.sync.aligned.m8n8.x2.trans.shared.b16 {%0,%1}, [%2];"
                        : "=r"(b0), "=r"(b1) : "r"(baddr));
                    asm volatile("mma.sync.aligned.m16n8k16.row.col.f32.bf16.bf16.f32 "
                        "{%0,%1,%2,%3}, {%4,%5,%6,%7}, {%8,%9}, {%0,%1,%2,%3};"
                        : "+f"(acc[j][0]), "+f"(acc[j][1]), "+f"(acc[j][2]), "+f"(acc[j][3])
                        : "r"(a[0]), "r"(a[1]), "r"(a[2]), "r"(a[3]), "r"(b0), "r"(b1));
                }
            }
        }
    }

    float* outp = isK ? g_K : g_Q;
    int rq = lane >> 2, cq = (lane & 3)*2;
    #pragma unroll
    for (int h = 0; h < 2; h++){
        long n_ = rowbase + wr0 + rq + 8*h;
        int nn = (int)(n_ & (NSEQ-1));
        #pragma unroll
        for (int j = 0; j < 8; j++){
            int d0 = j*8 + cq;
            float v0 = acc[j][2*h], v1 = acc[j][2*h+1];
            float r0, r1;
            if (j < 4){ r0 = -acc[j+4][2*h]; r1 = -acc[j+4][2*h+1]; }
            else      { r0 =  acc[j-4][2*h]; r1 =  acc[j-4][2*h+1]; }
            float2 cs = *(const float2*)&cosb[nn*DDIM + d0];
            float2 sn = *(const float2*)&sinb[nn*DDIM + d0];
            float2 o = make_float2(fmaf(v0, cs.x, r0*sn.x), fmaf(v1, cs.y, r1*sn.y));
            *(float2*)&outp[n_*DDIM + d0] = o;
        }
    }
}

// ---------------- initial charge + zero recvT/rsT ----------------
__global__ void charge0_kernel(const float* __restrict__ feat,
                               const float* __restrict__ cw,
                               const float* __restrict__ cb)
{
    int warp = threadIdx.x >> 5, lane = threadIdx.x & 31;
    long n = (long)blockIdx.x*8 + warp;
    if (n >= BN) return;
    float sum = 0.f;
    for (int f = lane; f < FDIM; f += 32) sum = fmaf(feat[n*FDIM+f], cw[f], sum);
    #pragma unroll
    for (int o = 16; o > 0; o >>= 1) sum += __shfl_down_sync(0xffffffffu, sum, o);
    if (lane == 0){
        g_ch0[n] = sigmoidf_(sum + cb[0]);
        #pragma unroll
        for (int t = 0; t < 4; t++){ g_recvT[t][n] = 0.f; g_rsT[t][n] = 0.f; }
    }
}

// ---------------- gemm via mma.sync bf16 hi/lo: C' = QK^T*(log2e/8), masked ----------------
__global__ void __launch_bounds__(256) gemm_mma_kernel()
{
    extern __shared__ __nv_bfloat16 smb[];
    __nv_bfloat16* Qhi = smb;
    __nv_bfloat16* Qlo = smb + 128*SQ;
    __nv_bfloat16* Khi = smb + 2*128*SQ;
    __nv_bfloat16* Klo = smb + 3*128*SQ;

    int b = blockIdx.y;
    int ti, tj; tri_decode_(blockIdx.x, ti, tj);

    const float* Qb = g_Q + ((long)b*NSEQ + (long)ti*128)*DDIM;
    const float* Kb = g_K + ((long)b*NSEQ + (long)tj*128)*DDIM;
    int tid = threadIdx.x;
    for (int i = tid; i < 128*32; i += 256){
        int r = i >> 5, c2 = i & 31;
        float2 q = *(const float2*)&Qb[r*64 + c2*2];
        float2 k = *(const float2*)&Kb[r*64 + c2*2];
        int o = r*SQ + c2*2;
        __nv_bfloat16 qhx = __float2bfloat16_rn(q.x), qhy = __float2bfloat16_rn(q.y);
        __nv_bfloat16 khx = __float2bfloat16_rn(k.x), khy = __float2bfloat16_rn(k.y);
        __nv_bfloat16 qlx = __float2bfloat16_rn(q.x - __bfloat162float(qhx));
        __nv_bfloat16 qly = __float2bfloat16_rn(q.y - __bfloat162float(qhy));
        __nv_bfloat16 klx = __float2bfloat16_rn(k.x - __bfloat162float(khx));
        __nv_bfloat16 kly = __float2bfloat16_rn(k.y - __bfloat162float(khy));
        *(__nv_bfloat162*)&Qhi[o] = __nv_bfloat162(qhx, qhy);
        *(__nv_bfloat162*)&Qlo[o] = __nv_bfloat162(qlx, qly);
        *(__nv_bfloat162*)&Khi[o] = __nv_bfloat162(khx, khy);
        *(__nv_bfloat162*)&Klo[o] = __nv_bfloat162(klx, kly);
    }
    __syncthreads();

    int lane = tid & 31, w = tid >> 5;
    int wm = (w & 1)*64, wn = (w >> 1)*32;

    float c[4][4][4] = {};

    uint32_t qhi_b = smem_u32_(Qhi), qlo_b = smem_u32_(Qlo);
    uint32_t khi_b = smem_u32_(Khi), klo_b = smem_u32_(Klo);

    int ar = lane & 15, ac8 = lane >> 4;
    int br = lane & 7,  bc8 = (lane >> 3) & 1;

    #pragma unroll
    for (int combo = 0; combo < 3; combo++){
        uint32_t abase = (combo == 2) ? qlo_b : qhi_b;
        uint32_t bbase = (combo == 1) ? klo_b : khi_b;
        #pragma unroll
        for (int k0 = 0; k0 < 64; k0 += 16){
            uint32_t a[4][4], bf[4][2];
            #pragma unroll
            for (int i = 0; i < 4; i++){
                uint32_t addr = abase + (uint32_t)(((wm + i*16 + ar)*SQ + k0 + ac8*8)*2);
                asm volatile("ldmatrix.sync.aligned.m8n8.x4.shared.b16 {%0,%1,%2,%3}, [%4];"
                    : "=r"(a[i][0]), "=r"(a[i][1]), "=r"(a[i][2]), "=r"(a[i][3]) : "r"(addr));
            }
            #pragma unroll
            for (int j = 0; j < 4; j++){
                uint32_t addr = bbase + (uint32_t)(((wn + j*8 + br)*SQ + k0 + bc8*8)*2);
                asm volatile("ldmatrix.sync.aligned.m8n8.x2.shared.b16 {%0,%1}, [%2];"
                    : "=r"(bf[j][0]), "=r"(bf[j][1]) : "r"(addr));
            }
            #pragma unroll
            for (int i = 0; i < 4; i++)
                #pragma unroll
                for (int j = 0; j < 4; j++)
                    asm volatile("mma.sync.aligned.m16n8k16.row.col.f32.bf16.bf16.f32 "
                        "{%0,%1,%2,%3}, {%4,%5,%6,%7}, {%8,%9}, {%0,%1,%2,%3};"
                        : "+f"(c[i][j][0]), "+f"(c[i][j][1]), "+f"(c[i][j][2]), "+f"(c[i][j][3])
                        : "r"(a[i][0]), "r"(a[i][1]), "r"(a[i][2]), "r"(a[i][3]),
                          "r"(bf[j][0]), "r"(bf[j][1]));
        }
    }

    float* Cb = g_C + (size_t)b*NSEQ*NSEQ;
    bool diag = (ti == tj);
    int rq = lane >> 2, cq = (lane & 3)*2;
    #pragma unroll
    for (int i = 0; i < 4; i++){
        int lr0 = wm + i*16 + rq;
        #pragma unroll
        for (int j = 0; j < 4; j++){
            int lc = wn + j*8 + cq;
            float2 v0 = make_float2(c[i][j][0]*SCALE_LOG2E, c[i][j][1]*SCALE_LOG2E);
            float2 v1 = make_float2(c[i][j][2]*SCALE_LOG2E, c[i][j][3]*SCALE_LOG2E);
            if (diag){
                if (lr0 < lc)       v0.x = MASKVAL;
                if (lr0 < lc+1)     v0.y = MASKVAL;
                if (lr0+8 < lc)     v1.x = MASKVAL;
                if (lr0+8 < lc+1)   v1.y = MASKVAL;
            }
            size_t row0 = (size_t)(ti*128 + lr0);
            int col = tj*128 + lc;
            *(float2*)&Cb[row0*NSEQ + col] = v0;
            *(float2*)&Cb[(row0+8)*NSEQ + col] = v1;
        }
    }
}

// ---------------- rowsum: compact 128x128 triangular tiles, charge chain in prologue ----------------
template<int T>
__global__ void __launch_bounds__(256) rowsum_kernel(const float* __restrict__ cdp,
                                                     const float* __restrict__ ssp)
{
    __shared__ float qcol[(T>0)?T:1][128];
    __shared__ float qrow[(T>0)?T:1][128];
    int b = blockIdx.y;
    int ti, tj; tri_decode_(blockIdx.x, ti, tj);
    int n0 = ti*128, m0 = tj*128;
    int tid = threadIdx.x;

    if (T > 0){
        float cd = __ldg(cdp);
        float sq = sqrtf(__ldg(ssp));
        int base = (tid < 128) ? m0 : n0;
        int li = tid & 127;
        int gi = b*NSEQ + base + li;
        float ch = g_ch0[gi];
        #pragma unroll
        for (int u = 0; u < T; u++){
            ch *= 1.f - cd*sigmoidf_(g_recvT[u][gi] - 1.f);
            if (tid < 128) qcol[u][li] = sq*ch; else qrow[u][li] = sq*ch;
        }
        __syncthreads();
    }

    int lane = tid & 31, w = tid >> 5;
    const float* Cb = g_C + (size_t)b*NSEQ*NSEQ;
    float4 q[(T>0)?T:1];
    #pragma unroll
    for (int u = 0; u < T; u++) q[u] = *(float4*)&qcol[u][lane*4];

    #pragma unroll
    for (int half = 0; half < 2; half++){
        int rbase = w*16 + half*8;
        float acc[8] = {0.f,0.f,0.f,0.f,0.f,0.f,0.f,0.f};
        #pragma unroll
        for (int r = 0; r < 8; r++){
            int n = n0 + rbase + r;
            float4 cc = __ldg((const float4*)&Cb[(size_t)n*NSEQ + m0 + lane*4]);
            float fx = 1.f, fy = 1.f, fz = 1.f, fw = 1.f;
            #pragma unroll
            for (int u = 0; u < T; u++){
                float cn = qrow[u][rbase+r];
                fx = fmaf(cn, q[u].x, fx);
                fy = fmaf(cn, q[u].y, fy);
                fz = fmaf(cn, q[u].z, fz);
                fw = fmaf(cn, q[u].w, fw);
            }
            float e0 = (T==0) ? ex2_(cc.x) : ex2_(cc.x*fx);
            float e1 = (T==0) ? ex2_(cc.y) : ex2_(cc.y*fy);
            float e2 = (T==0) ? ex2_(cc.z) : ex2_(cc.z*fz);
            float e3 = (T==0) ? ex2_(cc.w) : ex2_(cc.w*fw);
            acc[r] += (e0 + e1) + (e2 + e3);
        }
        #pragma unroll
        for (int r = 0; r < 8; r++){
            float s = acc[r];
            #pragma unroll
            for (int o = 16; o > 0; o >>= 1) s += __shfl_down_sync(0xffffffffu, s, o);
            if (lane == 0) atomicAdd(&g_rsT[T][b*NSEQ + n0 + rbase + r], s);
        }
    }
}

// ---------------- colsum: compact 128x128 triangular tiles ----------------
template<int T>
__global__ void __launch_bounds__(256) colsum_kernel(const float* __restrict__ cdp,
                                                     const float* __restrict__ ssp)
{
    __shared__ float qcol[(T>0)?T:1][128];
    __shared__ float qrow[(T>0)?T:1][128];
    __shared__ float irsrow[128];
    int b = blockIdx.y;
    int ti, tj; tri_decode_(blockIdx.x, ti, tj);
    int n0 = ti*128, m0 = tj*128;
    int tid = threadIdx.x;

    {
        float cd = __ldg(cdp);
        float sq = sqrtf(__ldg(ssp));
        int base = (tid < 128) ? m0 : n0;
        int li = tid & 127;
        int gi = b*NSEQ + base + li;
        if (tid >= 128) irsrow[li] = __frcp_rn(g_rsT[T][gi]);
        if (T > 0){
            float ch = g_ch0[gi];
            #pragma unroll
            for (int u = 0; u < T; u++){
                ch *= 1.f - cd*sigmoidf_(g_recvT[u][gi] - 1.f);
                if (tid < 128) qcol[u][li] = sq*ch; else qrow[u][li] = sq*ch;
            }
        }
        __syncthreads();
    }

    int lane = tid & 31, w = tid >> 5;
    int m = m0 + lane*4;
    const float* Cb = g_C + (size_t)b*NSEQ*NSEQ;
    float4 q[(T>0)?T:1];
    #pragma unroll
    for (int u = 0; u < T; u++) q[u] = *(float4*)&qcol[u][lane*4];
    float4 acc = make_float4(0.f,0.f,0.f,0.f);
    #pragma unroll 4
    for (int r = 0; r < 16; r++){
        int rr = w*16 + r;
        int n = n0 + rr;
        float irs = irsrow[rr];
        float4 cc = __ldg((const float4*)&Cb[(size_t)n*NSEQ + m]);
        float fx = 1.f, fy = 1.f, fz = 1.f, fw = 1.f;
        #pragma unroll
        for (int u = 0; u < T; u++){
            float cn = qrow[u][rr];
            fx = fmaf(cn, q[u].x, fx);
            fy = fmaf(cn, q[u].y, fy);
            fz = fmaf(cn, q[u].z, fz);
            fw = fmaf(cn, q[u].w, fw);
        }
        acc.x += ((T==0) ? ex2_(cc.x) : ex2_(cc.x*fx))*irs;
        acc.y += ((T==0) ? ex2_(cc.y) : ex2_(cc.y*fy))*irs;
        acc.z += ((T==0) ? ex2_(cc.z) : ex2_(cc.z*fz))*irs;
        acc.w += ((T==0) ? ex2_(cc.w) : ex2_(cc.w*fw))*irs;
    }
    __shared__ float4 s4[256];
    s4[tid] = acc;
    __syncthreads();
    if (tid < 32){
        float4 t = s4[tid];
        #pragma unroll
        for (int r = 1; r < 8; r++){
            float4 o = s4[tid + r*32];
            t.x += o.x; t.y += o.y; t.z += o.z; t.w += o.w;
        }
        float* dst = &g_recvT[T][b*NSEQ + m0 + tid*4];
        atomicAdd(dst+0, t.x);
        atomicAdd(dst+1, t.y);
        atomicAdd(dst+2, t.z);
        atomicAdd(dst+3, t.w);
    }
}

// ---------------- fused final: charge chain + rowsum + normalized write ----------------
__global__ void __launch_bounds__(256) final_fused_kernel(float* __restrict__ out,
                                                          const float* __restrict__ cdp,
                                                          const float* __restrict__ ssp)
{
    extern __shared__ float fsm[];
    float* qc = fsm;             // [4][NSEQ]
    float* P  = fsm + 4*NSEQ;    // [NSEQ]
    __shared__ float red[9];
    int blk = blockIdx.x;
    int b = blk & 1;
    int n = (NSEQ-1) - (blk >> 1);           // long rows first
    int tid = threadIdx.x, lane = tid & 31, wid = tid >> 5;

    // prologue: full charge chain for all columns
    {
        float cd = __ldg(cdp);
        float sq = sqrtf(__ldg(ssp));
        for (int i = tid; i < NSEQ; i += 256){
            int gi = b*NSEQ + i;
            float ch = g_ch0[gi];
            #pragma unroll
            for (int u = 0; u < 4; u++){
                ch *= 1.f - cd*sigmoidf_(g_recvT[u][gi] - 1.f);
                qc[u*NSEQ + i] = sq*ch;
            }
        }
        __syncthreads();
    }

    const float* Crow = g_C + ((size_t)b*NSEQ + n)*NSEQ;
    int L = ((n >> 7) + 1) << 7;             // row length rounded up to 128 (masked tail ~ 0)
    float cn0 = qc[0*NSEQ + n];
    float cn1 = qc[1*NSEQ + n];
    float cn2 = qc[2*NSEQ + n];
    float cn3 = qc[3*NSEQ + n];
    float sum = 0.f;
    for (int i = tid; i < (L >> 2); i += 256){
        float4 cc = __ldg(&((const float4*)Crow)[i]);
        int m = i*4;
        float4 t0 = *(float4*)&qc[0*NSEQ + m];
        float4 t1 = *(float4*)&qc[1*NSEQ + m];
        float4 t2 = *(float4*)&qc[2*NSEQ + m];
        float4 t3 = *(float4*)&qc[3*NSEQ + m];
        float fx = fmaf(cn0,t0.x, fmaf(cn1,t1.x, fmaf(cn2,t2.x, fmaf(cn3,t3.x, 1.f))));
        float fy = fmaf(cn0,t0.y, fmaf(cn1,t1.y, fmaf(cn2,t2.y, fmaf(cn3,t3.y, 1.f))));
        float fz = fmaf(cn0,t0.z, fmaf(cn1,t1.z, fmaf(cn2,t2.z, fmaf(cn3,t3.z, 1.f))));
        float fw = fmaf(cn0,t0.w, fmaf(cn1,t1.w, fmaf(cn2,t2.w, fmaf(cn3,t3.w, 1.f))));
        float p0 = ex2_(cc.x*fx), p1 = ex2_(cc.y*fy);
        float p2 = ex2_(cc.z*fz), p3 = ex2_(cc.w*fw);
        *(float4*)&P[m] = make_float4(p0,p1,p2,p3);
        sum += (p0 + p1) + (p2 + p3);
    }
    #pragma unroll
    for (int o = 16; o > 0; o >>= 1) sum += __shfl_down_sync(0xffffffffu, sum, o);
    if (lane == 0) red[wid] = sum;
    __syncthreads();
    if (tid == 0){
        float s = 0.f;
        #pragma unroll
        for (int w = 0; w < 8; w++) s += red[w];
        red[8] = 1.f / s;
    }
    __syncthreads();
    float irs = red[8];
    float* orow = out + ((size_t)b*NSEQ + n)*NSEQ;
    int L4 = L >> 2;
    for (int i = tid; i < NSEQ/4; i += 256){
        float4 v = make_float4(0.f,0.f,0.f,0.f);
        if (i < L4){
            float4 p = *(float4*)&P[i*4];
            v = make_float4(p.x*irs, p.y*irs, p.z*irs, p.w*irs);
        }
        __stcs((float4*)&orow[i*4], v);
    }
}

// ---------------- launch ----------------
extern "C" void kernel_launch(void* const* d_in, const int* in_sizes, int n_in,
                              void* d_out, int out_size)
{
    const float* feat = (const float*)d_in[0];
    const float* cosb = (const float*)d_in[1];
    const float* sinb = (const float*)d_in[2];
    // d_in[3] = mask (causal; not needed)
    const float* Wq   = (const float*)d_in[4];
    const float* Wk   = (const float*)d_in[5];
    const float* cw   = (const float*)d_in[6];
    const float* cb   = (const float*)d_in[7];
    const float* ssp  = (const float*)d_in[8];
    const float* cdp  = (const float*)d_in[9];
    float* out = (float*)d_out;

    const int GSMEM  = 4*128*SQ*2;               // 73728 bytes
    const int FSMEM  = (4*NSEQ + NSEQ)*4;        // 81920 bytes
    static int smem_set = 0;
    if (!smem_set){
        cudaFuncSetAttribute(gemm_mma_kernel, cudaFuncAttributeMaxDynamicSharedMemorySize, GSMEM);
        cudaFuncSetAttribute(qk_mma_kernel, cudaFuncAttributeMaxDynamicSharedMemorySize, QK_SMEM_B);
        cudaFuncSetAttribute(final_fused_kernel, cudaFuncAttributeMaxDynamicSharedMemorySize, FSMEM);
        smem_set = 1;
    }

    qk_mma_kernel<<<BN/64, 256, QK_SMEM_B>>>(feat, cosb, sinb, Wq, Wk);
    charge0_kernel<<<BN/8, 256>>>(feat, cw, cb);

    const int T = NSEQ/128;
    dim3 gtri(T*(T+1)/2, BATCH);
    gemm_mma_kernel<<<gtri, 256, GSMEM>>>();

    rowsum_kernel<0><<<gtri, 256>>>(cdp, ssp);
    colsum_kernel<0><<<gtri, 256>>>(cdp, ssp);
    rowsum_kernel<1><<<gtri, 256>>>(cdp, ssp);
    colsum_kernel<1><<<gtri, 256>>>(cdp, ssp);
    rowsum_kernel<2><<<gtri, 256>>>(cdp, ssp);
    colsum_kernel<2><<<gtri, 256>>>(cdp, ssp);
    rowsum_kernel<3><<<gtri, 256>>>(cdp, ssp);
    colsum_kernel<3><<<gtri, 256>>>(cdp, ssp);

    final_fused_kernel<<<BN, 256, FSMEM>>>(out, cdp, ssp);
}

// round 14
// speedup vs baseline: 2.5525x; 2.5525x over previous
#include <cuda_runtime.h>
#include <cuda_bf16.h>
#include <cstdint>
#include <math.h>

#define NSEQ 4096
#define BATCH 2
#define BN (BATCH*NSEQ)
#define FDIM 512
#define DDIM 64
#define MASKVAL (-12800.0f)
#define SCALE_LOG2E (0.125f*1.4426950408889634f)
#define SQ 72   // padded bf16 row stride for mma smem tiles

// ---------------- scratch (device globals; no allocation allowed) ----------------
__device__ float g_Q[(size_t)BN*DDIM];
__device__ float g_K[(size_t)BN*DDIM];
__device__ float g_C[(size_t)BATCH*NSEQ*NSEQ];   // C' = (QK^T/8)*log2e; above-diag of diag tiles = MASKVAL
__device__ float g_ch[BN];                       // current charge
__device__ float g_chpt[4][BN];                  // packed sqrt(ss)*charge history
__device__ float g_rsT[4][BN];                   // row sums per iteration
__device__ float g_recv[BN];                     // received accumulator (zeroed by chargeupd)

__device__ __forceinline__ float sigmoidf_(float x){ return 1.f/(1.f+__expf(-x)); }
__device__ __forceinline__ float ex2_(float x){ float y; asm("ex2.approx.f32 %0, %1;" : "=f"(y) : "f"(x)); return y; }
__device__ __forceinline__ uint32_t smem_u32_(const void* p){
    uint32_t a;
    asm("{ .reg .u64 t; cvta.to.shared.u64 t, %1; cvt.u32.u64 %0, t; }" : "=r"(a) : "l"(p));
    return a;
}
__device__ __forceinline__ void tri_decode_(int kidx, int& ti, int& tj){
    int t = (int)((sqrtf(8.f*(float)kidx + 1.f) - 1.f) * 0.5f);
    while ((t+1)*(t+2)/2 <= kidx) t++;
    while (t*(t+1)/2 > kidx) t--;
    ti = t; tj = kidx - t*(t+1)/2;
}

// ---------------- Q/K projection via mma.sync bf16 hi/lo + in-register RoPE ----------------
#define QK_SMEM_B (27648*2)

__global__ void __launch_bounds__(256) qk_mma_kernel(const float* __restrict__ feat,
                                                     const float* __restrict__ cosb,
                                                     const float* __restrict__ sinb,
                                                     const float* __restrict__ Wq,
                                                     const float* __restrict__ Wk)
{
    extern __shared__ __nv_bfloat16 sm[];
    __nv_bfloat16* Ahi = sm;
    __nv_bfloat16* Alo = sm + 4608;
    int tid = threadIdx.x, lane = tid & 31, w = tid >> 5;
    long rowbase = (long)blockIdx.x*64;
    int isK = w >> 2;
    int wr0 = (w & 3)*16;
    float acc[8][4] = {};

    for (int f0 = 0; f0 < FDIM; f0 += 64){
        __syncthreads();
        for (int i = tid; i < 64*32; i += 256){
            int r = i >> 5, c2 = i & 31;
            float2 v = *(const float2*)&feat[(rowbase + r)*FDIM + f0 + c2*2];
            __nv_bfloat16 hx = __float2bfloat16_rn(v.x), hy = __float2bfloat16_rn(v.y);
            __nv_bfloat16 lx = __float2bfloat16_rn(v.x - __bfloat162float(hx));
            __nv_bfloat16 ly = __float2bfloat16_rn(v.y - __bfloat162float(hy));
            int o = r*SQ + c2*2;
            *(__nv_bfloat162*)&Ahi[o] = __nv_bfloat162(hx, hy);
            *(__nv_bfloat162*)&Alo[o] = __nv_bfloat162(lx, ly);
        }
        for (int i = tid; i < 64*32; i += 256){
            int f = i >> 5, c2 = i & 31;
            float2 q = *(const float2*)&Wq[(f0+f)*DDIM + c2*2];
            float2 k = *(const float2*)&Wk[(f0+f)*DDIM + c2*2];
            int o = f*SQ + c2*2;
            __nv_bfloat16 qhx = __float2bfloat16_rn(q.x), qhy = __float2bfloat16_rn(q.y);
            __nv_bfloat16 khx = __float2bfloat16_rn(k.x), khy = __float2bfloat16_rn(k.y);
            __nv_bfloat16 qlx = __float2bfloat16_rn(q.x - __bfloat162float(qhx));
            __nv_bfloat16 qly = __float2bfloat16_rn(q.y - __bfloat162float(qhy));
            __nv_bfloat16 klx = __float2bfloat16_rn(k.x - __bfloat162float(khx));
            __nv_bfloat16 kly = __float2bfloat16_rn(k.y - __bfloat162float(khy));
            *(__nv_bfloat162*)&sm[ 9216 + o] = __nv_bfloat162(qhx, qhy);
            *(__nv_bfloat162*)&sm[13824 + o] = __nv_bfloat162(qlx, qly);
            *(__nv_bfloat162*)&sm[18432 + o] = __nv_bfloat162(khx, khy);
            *(__nv_bfloat162*)&sm[23040 + o] = __nv_bfloat162(klx, kly);
        }
        __syncthreads();

        uint32_t a_hi = smem_u32_(Ahi), a_lo = smem_u32_(Alo);
        uint32_t b_hi = smem_u32_(sm + (isK ? 18432 : 9216));
        uint32_t b_lo = smem_u32_(sm + (isK ? 23040 : 13824));
        #pragma unroll
        for (int combo = 0; combo < 3; combo++){
            uint32_t abase = (combo == 2) ? a_lo : a_hi;
            uint32_t bbase = (combo == 1) ? b_lo : b_hi;
            #pragma unroll
            for (int k0 = 0; k0 < 64; k0 += 16){
                uint32_t a[4];
                uint32_t aaddr = abase + (uint32_t)(((wr0 + (lane & 15))*SQ + k0 + (lane >> 4)*8)*2);
                asm volatile("ldmatrix.sync.aligned.m8n8.x4.shared.b16 {%0,%1,%2,%3}, [%4];"
                    : "=r"(a[0]), "=r"(a[1]), "=r"(a[2]), "=r"(a[3]) : "r"(aaddr));
                #pragma unroll
                for (int j = 0; j < 8; j++){
                    uint32_t b0, b1;
                    uint32_t baddr = bbase + (uint32_t)(((k0 + (lane & 15))*SQ + j*8)*2);
                    asm volatile("ldmatrix.sync.aligned.m8n8.x2.trans.shared.b16 {%0,%1}, [%2];"
                        : "=r"(b0), "=r"(b1) : "r"(baddr));
                    asm volatile("mma.sync.aligned.m16n8k16.row.col.f32.bf16.bf16.f32 "
                        "{%0,%1,%2,%3}, {%4,%5,%6,%7}, {%8,%9}, {%0,%1,%2,%3};"
                        : "+f"(acc[j][0]), "+f"(acc[j][1]), "+f"(acc[j][2]), "+f"(acc[j][3])
                        : "r"(a[0]), "r"(a[1]), "r"(a[2]), "r"(a[3]), "r"(b0), "r"(b1));
                }
            }
        }
    }

    float* outp = isK ? g_K : g_Q;
    int rq = lane >> 2, cq = (lane & 3)*2;
    #pragma unroll
    for (int h = 0; h < 2; h++){
        long n_ = rowbase + wr0 + rq + 8*h;
        int nn = (int)(n_ & (NSEQ-1));
        #pragma unroll
        for (int j = 0; j < 8; j++){
            int d0 = j*8 + cq;
            float v0 = acc[j][2*h], v1 = acc[j][2*h+1];
            float r0, r1;
            if (j < 4){ r0 = -acc[j+4][2*h]; r1 = -acc[j+4][2*h+1]; }
            else      { r0 =  acc[j-4][2*h]; r1 =  acc[j-4][2*h+1]; }
            float2 cs = *(const float2*)&cosb[nn*DDIM + d0];
            float2 sn = *(const float2*)&sinb[nn*DDIM + d0];
            float2 o = make_float2(fmaf(v0, cs.x, r0*sn.x), fmaf(v1, cs.y, r1*sn.y));
            *(float2*)&outp[n_*DDIM + d0] = o;
        }
    }
}

// ---------------- initial charge + zero recv/rsT/chpt ----------------
__global__ void charge0_kernel(const float* __restrict__ feat,
                               const float* __restrict__ cw,
                               const float* __restrict__ cb)
{
    int warp = threadIdx.x >> 5, lane = threadIdx.x & 31;
    long n = (long)blockIdx.x*8 + warp;
    if (n >= BN) return;
    float sum = 0.f;
    for (int f = lane; f < FDIM; f += 32) sum = fmaf(feat[n*FDIM+f], cw[f], sum);
    #pragma unroll
    for (int o = 16; o > 0; o >>= 1) sum += __shfl_down_sync(0xffffffffu, sum, o);
    if (lane == 0){
        g_ch[n] = sigmoidf_(sum + cb[0]);
        g_recv[n] = 0.f;
        #pragma unroll
        for (int t = 0; t < 4; t++){ g_rsT[t][n] = 0.f; g_chpt[t][n] = 0.f; }
    }
}

// ---------------- gemm via mma.sync bf16 hi/lo: C' = QK^T*(log2e/8), masked ----------------
__global__ void __launch_bounds__(256) gemm_mma_kernel()
{
    extern __shared__ __nv_bfloat16 smb[];
    __nv_bfloat16* Qhi = smb;
    __nv_bfloat16* Qlo = smb + 128*SQ;
    __nv_bfloat16* Khi = smb + 2*128*SQ;
    __nv_bfloat16* Klo = smb + 3*128*SQ;

    int b = blockIdx.y;
    int ti, tj; tri_decode_(blockIdx.x, ti, tj);

    const float* Qb = g_Q + ((long)b*NSEQ + (long)ti*128)*DDIM;
    const float* Kb = g_K + ((long)b*NSEQ + (long)tj*128)*DDIM;
    int tid = threadIdx.x;
    for (int i = tid; i < 128*32; i += 256){
        int r = i >> 5, c2 = i & 31;
        float2 q = *(const float2*)&Qb[r*64 + c2*2];
        float2 k = *(const float2*)&Kb[r*64 + c2*2];
        int o = r*SQ + c2*2;
        __nv_bfloat16 qhx = __float2bfloat16_rn(q.x), qhy = __float2bfloat16_rn(q.y);
        __nv_bfloat16 khx = __float2bfloat16_rn(k.x), khy = __float2bfloat16_rn(k.y);
        __nv_bfloat16 qlx = __float2bfloat16_rn(q.x - __bfloat162float(qhx));
        __nv_bfloat16 qly = __float2bfloat16_rn(q.y - __bfloat162float(qhy));
        __nv_bfloat16 klx = __float2bfloat16_rn(k.x - __bfloat162float(khx));
        __nv_bfloat16 kly = __float2bfloat16_rn(k.y - __bfloat162float(khy));
        *(__nv_bfloat162*)&Qhi[o] = __nv_bfloat162(qhx, qhy);
        *(__nv_bfloat162*)&Qlo[o] = __nv_bfloat162(qlx, qly);
        *(__nv_bfloat162*)&Khi[o] = __nv_bfloat162(khx, khy);
        *(__nv_bfloat162*)&Klo[o] = __nv_bfloat162(klx, kly);
    }
    __syncthreads();

    int lane = tid & 31, w = tid >> 5;
    int wm = (w & 1)*64, wn = (w >> 1)*32;

    float c[4][4][4] = {};

    uint32_t qhi_b = smem_u32_(Qhi), qlo_b = smem_u32_(Qlo);
    uint32_t khi_b = smem_u32_(Khi), klo_b = smem_u32_(Klo);

    int ar = lane & 15, ac8 = lane >> 4;
    int br = lane & 7,  bc8 = (lane >> 3) & 1;

    #pragma unroll
    for (int combo = 0; combo < 3; combo++){
        uint32_t abase = (combo == 2) ? qlo_b : qhi_b;
        uint32_t bbase = (combo == 1) ? klo_b : khi_b;
        #pragma unroll
        for (int k0 = 0; k0 < 64; k0 += 16){
            uint32_t a[4][4], bf[4][2];
            #pragma unroll
            for (int i = 0; i < 4; i++){
                uint32_t addr = abase + (uint32_t)(((wm + i*16 + ar)*SQ + k0 + ac8*8)*2);
                asm volatile("ldmatrix.sync.aligned.m8n8.x4.shared.b16 {%0,%1,%2,%3}, [%4];"
                    : "=r"(a[i][0]), "=r"(a[i][1]), "=r"(a[i][2]), "=r"(a[i][3]) : "r"(addr));
            }
            #pragma unroll
            for (int j = 0; j < 4; j++){
                uint32_t addr = bbase + (uint32_t)(((wn + j*8 + br)*SQ + k0 + bc8*8)*2);
                asm volatile("ldmatrix.sync.aligned.m8n8.x2.shared.b16 {%0,%1}, [%2];"
                    : "=r"(bf[j][0]), "=r"(bf[j][1]) : "r"(addr));
            }
            #pragma unroll
            for (int i = 0; i < 4; i++)
                #pragma unroll
                for (int j = 0; j < 4; j++)
                    asm volatile("mma.sync.aligned.m16n8k16.row.col.f32.bf16.bf16.f32 "
                        "{%0,%1,%2,%3}, {%4,%5,%6,%7}, {%8,%9}, {%0,%1,%2,%3};"
                        : "+f"(c[i][j][0]), "+f"(c[i][j][1]), "+f"(c[i][j][2]), "+f"(c[i][j][3])
                        : "r"(a[i][0]), "r"(a[i][1]), "r"(a[i][2]), "r"(a[i][3]),
                          "r"(bf[j][0]), "r"(bf[j][1]));
        }
    }

    float* Cb = g_C + (size_t)b*NSEQ*NSEQ;
    bool diag = (ti == tj);
    int rq = lane >> 2, cq = (lane & 3)*2;
    #pragma unroll
    for (int i = 0; i < 4; i++){
        int lr0 = wm + i*16 + rq;
        #pragma unroll
        for (int j = 0; j < 4; j++){
            int lc = wn + j*8 + cq;
            float2 v0 = make_float2(c[i][j][0]*SCALE_LOG2E, c[i][j][1]*SCALE_LOG2E);
            float2 v1 = make_float2(c[i][j][2]*SCALE_LOG2E, c[i][j][3]*SCALE_LOG2E);
            if (diag){
                if (lr0 < lc)       v0.x = MASKVAL;
                if (lr0 < lc+1)     v0.y = MASKVAL;
                if (lr0+8 < lc)     v1.x = MASKVAL;
                if (lr0+8 < lc+1)   v1.y = MASKVAL;
            }
            size_t row0 = (size_t)(ti*128 + lr0);
            int col = tj*128 + lc;
            *(float2*)&Cb[row0*NSEQ + col] = v0;
            *(float2*)&Cb[(row0+8)*NSEQ + col] = v1;
        }
    }
}

// ---------------- rowsum: compact 128x128 triangular tiles ----------------
template<int T>
__global__ void __launch_bounds__(256) rowsum_kernel()
{
    __shared__ float qcol[(T>0)?T:1][128];
    __shared__ float qrow[(T>0)?T:1][128];
    int b = blockIdx.y;
    int ti, tj; tri_decode_(blockIdx.x, ti, tj);
    int n0 = ti*128, m0 = tj*128;
    int tid = threadIdx.x;

    if (T > 0){
        for (int i = tid; i < 128*T; i += 256){
            int u = i >> 7, li = i & 127;
            qcol[u][li] = g_chpt[u][b*NSEQ + m0 + li];
            qrow[u][li] = g_chpt[u][b*NSEQ + n0 + li];
        }
        __syncthreads();
    }

    int lane = tid & 31, w = tid >> 5;
    const float* Cb = g_C + (size_t)b*NSEQ*NSEQ;
    float4 q[(T>0)?T:1];
    #pragma unroll
    for (int u = 0; u < T; u++) q[u] = *(float4*)&qcol[u][lane*4];

    #pragma unroll
    for (int half = 0; half < 2; half++){
        int rbase = w*16 + half*8;
        float acc[8] = {0.f,0.f,0.f,0.f,0.f,0.f,0.f,0.f};
        #pragma unroll
        for (int r = 0; r < 8; r++){
            int n = n0 + rbase + r;
            float4 cc = __ldg((const float4*)&Cb[(size_t)n*NSEQ + m0 + lane*4]);
            float fx = 1.f, fy = 1.f, fz = 1.f, fw = 1.f;
            #pragma unroll
            for (int u = 0; u < T; u++){
                float cn = qrow[u][rbase+r];
                fx = fmaf(cn, q[u].x, fx);
                fy = fmaf(cn, q[u].y, fy);
                fz = fmaf(cn, q[u].z, fz);
                fw = fmaf(cn, q[u].w, fw);
            }
            float e0 = (T==0) ? ex2_(cc.x) : ex2_(cc.x*fx);
            float e1 = (T==0) ? ex2_(cc.y) : ex2_(cc.y*fy);
            float e2 = (T==0) ? ex2_(cc.z) : ex2_(cc.z*fz);
            float e3 = (T==0) ? ex2_(cc.w) : ex2_(cc.w*fw);
            acc[r] += (e0 + e1) + (e2 + e3);
        }
        #pragma unroll
        for (int r = 0; r < 8; r++){
            float s = acc[r];
            #pragma unroll
            for (int o = 16; o > 0; o >>= 1) s += __shfl_down_sync(0xffffffffu, s, o);
            if (lane == 0) atomicAdd(&g_rsT[T][b*NSEQ + n0 + rbase + r], s);
        }
    }
}

// ---------------- colsum: compact 128x128 triangular tiles ----------------
template<int T>
__global__ void __launch_bounds__(256) colsum_kernel()
{
    __shared__ float qcol[(T>0)?T:1][128];
    __shared__ float qrow[(T>0)?T:1][128];
    __shared__ float irsrow[128];
    int b = blockIdx.y;
    int ti, tj; tri_decode_(blockIdx.x, ti, tj);
    int n0 = ti*128, m0 = tj*128;
    int tid = threadIdx.x;

    if (tid < 128) irsrow[tid] = __frcp_rn(g_rsT[T][b*NSEQ + n0 + tid]);
    if (T > 0){
        for (int i = tid; i < 128*T; i += 256){
            int u = i >> 7, li = i & 127;
            qcol[u][li] = g_chpt[u][b*NSEQ + m0 + li];
            qrow[u][li] = g_chpt[u][b*NSEQ + n0 + li];
        }
    }
    __syncthreads();

    int lane = tid & 31, w = tid >> 5;
    int m = m0 + lane*4;
    const float* Cb = g_C + (size_t)b*NSEQ*NSEQ;
    float4 q[(T>0)?T:1];
    #pragma unroll
    for (int u = 0; u < T; u++) q[u] = *(float4*)&qcol[u][lane*4];
    float4 acc = make_float4(0.f,0.f,0.f,0.f);
    #pragma unroll 4
    for (int r = 0; r < 16; r++){
        int rr = w*16 + r;
        int n = n0 + rr;
        float irs = irsrow[rr];
        float4 cc = __ldg((const float4*)&Cb[(size_t)n*NSEQ + m]);
        float fx = 1.f, fy = 1.f, fz = 1.f, fw = 1.f;
        #pragma unroll
        for (int u = 0; u < T; u++){
            float cn = qrow[u][rr];
            fx = fmaf(cn, q[u].x, fx);
            fy = fmaf(cn, q[u].y, fy);
            fz = fmaf(cn, q[u].z, fz);
            fw = fmaf(cn, q[u].w, fw);
        }
        acc.x += ((T==0) ? ex2_(cc.x) : ex2_(cc.x*fx))*irs;
        acc.y += ((T==0) ? ex2_(cc.y) : ex2_(cc.y*fy))*irs;
        acc.z += ((T==0) ? ex2_(cc.z) : ex2_(cc.z*fz))*irs;
        acc.w += ((T==0) ? ex2_(cc.w) : ex2_(cc.w*fw))*irs;
    }
    __shared__ float4 s4[256];
    s4[tid] = acc;
    __syncthreads();
    if (tid < 32){
        float4 t = s4[tid];
        #pragma unroll
        for (int r = 1; r < 8; r++){
            float4 o = s4[tid + r*32];
            t.x += o.x; t.y += o.y; t.z += o.z; t.w += o.w;
        }
        float* dst = &g_recv[b*NSEQ + m0 + tid*4];
        atomicAdd(dst+0, t.x);
        atomicAdd(dst+1, t.y);
        atomicAdd(dst+2, t.z);
        atomicAdd(dst+3, t.w);
    }
}

// ---------------- charge update + pack + re-zero recv ----------------
__global__ void chargeupd_kernel(int t, const float* __restrict__ cdp,
                                        const float* __restrict__ ssp)
{
    int i = blockIdx.x*256 + threadIdx.x;
    if (i >= BN) return;
    float cd = *cdp, ss = *ssp;
    float r  = g_recv[i];
    float ch = g_ch[i] * (1.f - cd*sigmoidf_(r - 1.f));
    g_ch[i] = ch;
    g_chpt[t][i] = sqrtf(ss)*ch;
    g_recv[i] = 0.f;
}

// ---------------- fused final: row-strip rowsum + normalized write ----------------
__global__ void __launch_bounds__(256) final_fused_kernel(float* __restrict__ out)
{
    __shared__ float P[NSEQ];
    __shared__ float red[9];
    int blk = blockIdx.x;
    int b = blk & 1;
    int n = (NSEQ-1) - (blk >> 1);           // long rows first
    const float* Crow = g_C + ((size_t)b*NSEQ + n)*NSEQ;
    int tid = threadIdx.x, lane = tid & 31, wid = tid >> 5;
    int L = ((n >> 7) + 1) << 7;             // row length rounded up to 128 (masked tail ~ 0)
    float cn0 = g_chpt[0][b*NSEQ+n];
    float cn1 = g_chpt[1][b*NSEQ+n];
    float cn2 = g_chpt[2][b*NSEQ+n];
    float cn3 = g_chpt[3][b*NSEQ+n];
    float sum = 0.f;
    for (int i = tid; i < (L >> 2); i += 256){
        float4 cc = __ldg(&((const float4*)Crow)[i]);
        int m = b*NSEQ + i*4;
        float4 t0 = *(const float4*)&g_chpt[0][m];
        float4 t1 = *(const float4*)&g_chpt[1][m];
        float4 t2 = *(const float4*)&g_chpt[2][m];
        float4 t3 = *(const float4*)&g_chpt[3][m];
        float fx = fmaf(cn0,t0.x, fmaf(cn1,t1.x, fmaf(cn2,t2.x, fmaf(cn3,t3.x, 1.f))));
        float fy = fmaf(cn0,t0.y, fmaf(cn1,t1.y, fmaf(cn2,t2.y, fmaf(cn3,t3.y, 1.f))));
        float fz = fmaf(cn0,t0.z, fmaf(cn1,t1.z, fmaf(cn2,t2.z, fmaf(cn3,t3.z, 1.f))));
        float fw = fmaf(cn0,t0.w, fmaf(cn1,t1.w, fmaf(cn2,t2.w, fmaf(cn3,t3.w, 1.f))));
        float p0 = ex2_(cc.x*fx), p1 = ex2_(cc.y*fy);
        float p2 = ex2_(cc.z*fz), p3 = ex2_(cc.w*fw);
        *(float4*)&P[i*4] = make_float4(p0,p1,p2,p3);
        sum += (p0 + p1) + (p2 + p3);
    }
    #pragma unroll
    for (int o = 16; o > 0; o >>= 1) sum += __shfl_down_sync(0xffffffffu, sum, o);
    if (lane == 0) red[wid] = sum;
    __syncthreads();
    if (tid == 0){
        float s = 0.f;
        #pragma unroll
        for (int w = 0; w < 8; w++) s += red[w];
        red[8] = 1.f / s;
    }
    __syncthreads();
    float irs = red[8];
    float* orow = out + ((size_t)b*NSEQ + n)*NSEQ;
    int L4 = L >> 2;
    for (int i = tid; i < NSEQ/4; i += 256){
        float4 v = make_float4(0.f,0.f,0.f,0.f);
        if (i < L4){
            float4 p = *(float4*)&P[i*4];
            v = make_float4(p.x*irs, p.y*irs, p.z*irs, p.w*irs);
        }
        __stcs((float4*)&orow[i*4], v);
    }
}

// ---------------- launch ----------------
extern "C" void kernel_launch(void* const* d_in, const int* in_sizes, int n_in,
                              void* d_out, int out_size)
{
    const float* feat = (const float*)d_in[0];
    const float* cosb = (const float*)d_in[1];
    const float* sinb = (const float*)d_in[2];
    // d_in[3] = mask (causal; not needed)
    const float* Wq   = (const float*)d_in[4];
    const float* Wk   = (const float*)d_in[5];
    const float* cw   = (const float*)d_in[6];
    const float* cb   = (const float*)d_in[7];
    const float* ssp  = (const float*)d_in[8];
    const float* cdp  = (const float*)d_in[9];
    float* out = (float*)d_out;

    const int GSMEM = 4*128*SQ*2;   // 73728 bytes
    static int smem_set = 0;
    if (!smem_set){
        cudaFuncSetAttribute(gemm_mma_kernel, cudaFuncAttributeMaxDynamicSharedMemorySize, GSMEM);
        cudaFuncSetAttribute(qk_mma_kernel, cudaFuncAttributeMaxDynamicSharedMemorySize, QK_SMEM_B);
        smem_set = 1;
    }

    qk_mma_kernel<<<BN/64, 256, QK_SMEM_B>>>(feat, cosb, sinb, Wq, Wk);
    charge0_kernel<<<BN/8, 256>>>(feat, cw, cb);

    const int T = NSEQ/128;
    dim3 gtri(T*(T+1)/2, BATCH);
    gemm_mma_kernel<<<gtri, 256, GSMEM>>>();

    rowsum_kernel<0><<<gtri, 256>>>();
    colsum_kernel<0><<<gtri, 256>>>();
    chargeupd_kernel<<<BN/256, 256>>>(0, cdp, ssp);

    rowsum_kernel<1><<<gtri, 256>>>();
    colsum_kernel<1><<<gtri, 256>>>();
    chargeupd_kernel<<<BN/256, 256>>>(1, cdp, ssp);

    rowsum_kernel<2><<<gtri, 256>>>();
    colsum_kernel<2><<<gtri, 256>>>();
    chargeupd_kernel<<<BN/256, 256>>>(2, cdp, ssp);

    rowsum_kernel<3><<<gtri, 256>>>();
    colsum_kernel<3><<<gtri, 256>>>();
    chargeupd_kernel<<<BN/256, 256>>>(3, cdp, ssp);

    final_fused_kernel<<<BN, 256>>>(out);
}

// round 16
// speedup vs baseline: 2.7360x; 1.0719x over previous
#include <cuda_runtime.h>
#include <cuda_bf16.h>
#include <cuda_fp16.h>
#include <cstdint>
#include <math.h>

#define NSEQ 4096
#define BATCH 2
#define BN (BATCH*NSEQ)
#define FDIM 512
#define DDIM 64
#define MASKVAL (-30000.0f)
#define SCALE_LOG2E (0.125f*1.4426950408889634f)
#define SQ 72   // padded bf16 row stride for mma smem tiles

// ---------------- scratch (device globals; no allocation allowed) ----------------
__device__ float g_Q[(size_t)BN*DDIM];
__device__ float g_K[(size_t)BN*DDIM];
__device__ __half g_C[(size_t)BATCH*NSEQ*NSEQ]; // C' = (QK^T/8)*log2e fp16; above-diag of diag tiles = MASKVAL
__device__ float g_ch[BN];                       // current charge
__device__ float g_chpt[4][BN];                  // packed sqrt(ss)*charge history
__device__ float g_rsT[4][BN];                   // row sums per iteration
__device__ float g_recv[BN];                     // received accumulator (zeroed by chargeupd)

__device__ __forceinline__ float sigmoidf_(float x){ return 1.f/(1.f+__expf(-x)); }
__device__ __forceinline__ float ex2_(float x){ float y; asm("ex2.approx.f32 %0, %1;" : "=f"(y) : "f"(x)); return y; }
__device__ __forceinline__ uint32_t smem_u32_(const void* p){
    uint32_t a;
    asm("{ .reg .u64 t; cvta.to.shared.u64 t, %1; cvt.u32.u64 %0, t; }" : "=r"(a) : "l"(p));
    return a;
}
__device__ __forceinline__ void tri_decode_(int kidx, int& ti, int& tj){
    int t = (int)((sqrtf(8.f*(float)kidx + 1.f) - 1.f) * 0.5f);
    while ((t+1)*(t+2)/2 <= kidx) t++;
    while (t*(t+1)/2 > kidx) t--;
    ti = t; tj = kidx - t*(t+1)/2;
}
// load 4 consecutive fp16 C values as float4
__device__ __forceinline__ float4 ldC4_(const __half* p){
    uint2 u = __ldg((const uint2*)p);
    __half2 h01 = *reinterpret_cast<__half2*>(&u.x);
    __half2 h23 = *reinterpret_cast<__half2*>(&u.y);
    float2 a = __half22float2(h01);
    float2 b = __half22float2(h23);
    return make_float4(a.x, a.y, b.x, b.y);
}

// ---------------- Q/K projection via mma.sync bf16 hi/lo + in-register RoPE ----------------
#define QK_SMEM_B (27648*2)

__global__ void __launch_bounds__(256) qk_mma_kernel(const float* __restrict__ feat,
                                                     const float* __restrict__ cosb,
                                                     const float* __restrict__ sinb,
                                                     const float* __restrict__ Wq,
                                                     const float* __restrict__ Wk)
{
    extern __shared__ __nv_bfloat16 sm[];
    __nv_bfloat16* Ahi = sm;
    __nv_bfloat16* Alo = sm + 4608;
    int tid = threadIdx.x, lane = tid & 31, w = tid >> 5;
    long rowbase = (long)blockIdx.x*64;
    int isK = w >> 2;
    int wr0 = (w & 3)*16;
    float acc[8][4] = {};

    for (int f0 = 0; f0 < FDIM; f0 += 64){
        __syncthreads();
        for (int i = tid; i < 64*32; i += 256){
            int r = i >> 5, c2 = i & 31;
            float2 v = *(const float2*)&feat[(rowbase + r)*FDIM + f0 + c2*2];
            __nv_bfloat16 hx = __float2bfloat16_rn(v.x), hy = __float2bfloat16_rn(v.y);
            __nv_bfloat16 lx = __float2bfloat16_rn(v.x - __bfloat162float(hx));
            __nv_bfloat16 ly = __float2bfloat16_rn(v.y - __bfloat162float(hy));
            int o = r*SQ + c2*2;
            *(__nv_bfloat162*)&Ahi[o] = __nv_bfloat162(hx, hy);
            *(__nv_bfloat162*)&Alo[o] = __nv_bfloat162(lx, ly);
        }
        for (int i = tid; i < 64*32; i += 256){
            int f = i >> 5, c2 = i & 31;
            float2 q = *(const float2*)&Wq[(f0+f)*DDIM + c2*2];
            float2 k = *(const float2*)&Wk[(f0+f)*DDIM + c2*2];
            int o = f*SQ + c2*2;
            __nv_bfloat16 qhx = __float2bfloat16_rn(q.x), qhy = __float2bfloat16_rn(q.y);
            __nv_bfloat16 khx = __float2bfloat16_rn(k.x), khy = __float2bfloat16_rn(k.y);
            __nv_bfloat16 qlx = __float2bfloat16_rn(q.x - __bfloat162float(qhx));
            __nv_bfloat16 qly = __float2bfloat16_rn(q.y - __bfloat162float(qhy));
            __nv_bfloat16 klx = __float2bfloat16_rn(k.x - __bfloat162float(khx));
            __nv_bfloat16 kly = __float2bfloat16_rn(k.y - __bfloat162float(khy));
            *(__nv_bfloat162*)&sm[ 9216 + o] = __nv_bfloat162(qhx, qhy);
            *(__nv_bfloat162*)&sm[13824 + o] = __nv_bfloat162(qlx, qly);
            *(__nv_bfloat162*)&sm[18432 + o] = __nv_bfloat162(khx, khy);
            *(__nv_bfloat162*)&sm[23040 + o] = __nv_bfloat162(klx, kly);
        }
        __syncthreads();

        uint32_t a_hi = smem_u32_(Ahi), a_lo = smem_u32_(Alo);
        uint32_t b_hi = smem_u32_(sm + (isK ? 18432 : 9216));
        uint32_t b_lo = smem_u32_(sm + (isK ? 23040 : 13824));
        #pragma unroll
        for (int combo = 0; combo < 3; combo++){
            uint32_t abase = (combo == 2) ? a_lo : a_hi;
            uint32_t bbase = (combo == 1) ? b_lo : b_hi;
            #pragma unroll
            for (int k0 = 0; k0 < 64; k0 += 16){
                uint32_t a[4];
                uint32_t aaddr = abase + (uint32_t)(((wr0 + (lane & 15))*SQ + k0 + (lane >> 4)*8)*2);
                asm volatile("ldmatrix.sync.aligned.m8n8.x4.shared.b16 {%0,%1,%2,%3}, [%4];"
                    : "=r"(a[0]), "=r"(a[1]), "=r"(a[2]), "=r"(a[3]) : "r"(aaddr));
                #pragma unroll
                for (int j = 0; j < 8; j++){
                    uint32_t b0, b1;
                    uint32_t baddr = bbase + (uint32_t)(((k0 + (lane & 15))*SQ + j*8)*2);
                    asm volatile("ldmatrix.sync.aligned.m8n8.x2.trans.shared.b16 {%0,%1}, [%2];"
                        : "=r"(b0), "=r"(b1) : "r"(baddr));
                    asm volatile("mma.sync.aligned.m16n8k16.row.col.f32.bf16.bf16.f32 "
                        "{%0,%1,%2,%3}, {%4,%5,%6,%7}, {%8,%9}, {%0,%1,%2,%3};"
                        : "+f"(acc[j][0]), "+f"(acc[j][1]), "+f"(acc[j][2]), "+f"(acc[j][3])
                        : "r"(a[0]), "r"(a[1]), "r"(a[2]), "r"(a[3]), "r"(b0), "r"(b1));
                }
            }
        }
    }

    float* outp = isK ? g_K : g_Q;
    int rq = lane >> 2, cq = (lane & 3)*2;
    #pragma unroll
    for (int h = 0; h < 2; h++){
        long n_ = rowbase + wr0 + rq + 8*h;
        int nn = (int)(n_ & (NSEQ-1));
        #pragma unroll
        for (int j = 0; j < 8; j++){
            int d0 = j*8 + cq;
            float v0 = acc[j][2*h], v1 = acc[j][2*h+1];
            float r0, r1;
            if (j < 4){ r0 = -acc[j+4][2*h]; r1 = -acc[j+4][2*h+1]; }
            else      { r0 =  acc[j-4][2*h]; r1 =  acc[j-4][2*h+1]; }
            float2 cs = *(const float2*)&cosb[nn*DDIM + d0];
            float2 sn = *(const float2*)&sinb[nn*DDIM + d0];
            float2 o = make_float2(fmaf(v0, cs.x, r0*sn.x), fmaf(v1, cs.y, r1*sn.y));
            *(float2*)&outp[n_*DDIM + d0] = o;
        }
    }
}

// ---------------- initial charge + zero recv/rsT/chpt ----------------
__global__ void charge0_kernel(const float* __restrict__ feat,
                               const float* __restrict__ cw,
                               const float* __restrict__ cb)
{
    int warp = threadIdx.x >> 5, lane = threadIdx.x & 31;
    long n = (long)blockIdx.x*8 + warp;
    if (n >= BN) return;
    float sum = 0.f;
    for (int f = lane; f < FDIM; f += 32) sum = fmaf(feat[n*FDIM+f], cw[f], sum);
    #pragma unroll
    for (int o = 16; o > 0; o >>= 1) sum += __shfl_down_sync(0xffffffffu, sum, o);
    if (lane == 0){
        g_ch[n] = sigmoidf_(sum + cb[0]);
        g_recv[n] = 0.f;
        #pragma unroll
        for (int t = 0; t < 4; t++){ g_rsT[t][n] = 0.f; g_chpt[t][n] = 0.f; }
    }
}

// ---------------- gemm via mma.sync bf16 hi/lo: C' = QK^T*(log2e/8) fp16, masked ----------------
__global__ void __launch_bounds__(256) gemm_mma_kernel()
{
    extern __shared__ __nv_bfloat16 smb[];
    __nv_bfloat16* Qhi = smb;
    __nv_bfloat16* Qlo = smb + 128*SQ;
    __nv_bfloat16* Khi = smb + 2*128*SQ;
    __nv_bfloat16* Klo = smb + 3*128*SQ;

    int b = blockIdx.y;
    int ti, tj; tri_decode_(blockIdx.x, ti, tj);

    const float* Qb = g_Q + ((long)b*NSEQ + (long)ti*128)*DDIM;
    const float* Kb = g_K + ((long)b*NSEQ + (long)tj*128)*DDIM;
    int tid = threadIdx.x;
    for (int i = tid; i < 128*32; i += 256){
        int r = i >> 5, c2 = i & 31;
        float2 q = *(const float2*)&Qb[r*64 + c2*2];
        float2 k = *(const float2*)&Kb[r*64 + c2*2];
        int o = r*SQ + c2*2;
        __nv_bfloat16 qhx = __float2bfloat16_rn(q.x), qhy = __float2bfloat16_rn(q.y);
        __nv_bfloat16 khx = __float2bfloat16_rn(k.x), khy = __float2bfloat16_rn(k.y);
        __nv_bfloat16 qlx = __float2bfloat16_rn(q.x - __bfloat162float(qhx));
        __nv_bfloat16 qly = __float2bfloat16_rn(q.y - __bfloat162float(qhy));
        __nv_bfloat16 klx = __float2bfloat16_rn(k.x - __bfloat162float(khx));
        __nv_bfloat16 kly = __float2bfloat16_rn(k.y - __bfloat162float(khy));
        *(__nv_bfloat162*)&Qhi[o] = __nv_bfloat162(qhx, qhy);
        *(__nv_bfloat162*)&Qlo[o] = __nv_bfloat162(qlx, qly);
        *(__nv_bfloat162*)&Khi[o] = __nv_bfloat162(khx, khy);
        *(__nv_bfloat162*)&Klo[o] = __nv_bfloat162(klx, kly);
    }
    __syncthreads();

    int lane = tid & 31, w = tid >> 5;
    int wm = (w & 1)*64, wn = (w >> 1)*32;

    float c[4][4][4] = {};

    uint32_t qhi_b = smem_u32_(Qhi), qlo_b = smem_u32_(Qlo);
    uint32_t khi_b = smem_u32_(Khi), klo_b = smem_u32_(Klo);

    int ar = lane & 15, ac8 = lane >> 4;
    int br = lane & 7,  bc8 = (lane >> 3) & 1;

    #pragma unroll
    for (int combo = 0; combo < 3; combo++){
        uint32_t abase = (combo == 2) ? qlo_b : qhi_b;
        uint32_t bbase = (combo == 1) ? klo_b : khi_b;
        #pragma unroll
        for (int k0 = 0; k0 < 64; k0 += 16){
            uint32_t a[4][4], bf[4][2];
            #pragma unroll
            for (int i = 0; i < 4; i++){
                uint32_t addr = abase + (uint32_t)(((wm + i*16 + ar)*SQ + k0 + ac8*8)*2);
                asm volatile("ldmatrix.sync.aligned.m8n8.x4.shared.b16 {%0,%1,%2,%3}, [%4];"
                    : "=r"(a[i][0]), "=r"(a[i][1]), "=r"(a[i][2]), "=r"(a[i][3]) : "r"(addr));
            }
            #pragma unroll
            for (int j = 0; j < 4; j++){
                uint32_t addr = bbase + (uint32_t)(((wn + j*8 + br)*SQ + k0 + bc8*8)*2);
                asm volatile("ldmatrix.sync.aligned.m8n8.x2.shared.b16 {%0,%1}, [%2];"
                    : "=r"(bf[j][0]), "=r"(bf[j][1]) : "r"(addr));
            }
            #pragma unroll
            for (int i = 0; i < 4; i++)
                #pragma unroll
                for (int j = 0; j < 4; j++)
                    asm volatile("mma.sync.aligned.m16n8k16.row.col.f32.bf16.bf16.f32 "
                        "{%0,%1,%2,%3}, {%4,%5,%6,%7}, {%8,%9}, {%0,%1,%2,%3};"
                        : "+f"(c[i][j][0]), "+f"(c[i][j][1]), "+f"(c[i][j][2]), "+f"(c[i][j][3])
                        : "r"(a[i][0]), "r"(a[i][1]), "r"(a[i][2]), "r"(a[i][3]),
                          "r"(bf[j][0]), "r"(bf[j][1]));
        }
    }

    __half* Cb = g_C + (size_t)b*NSEQ*NSEQ;
    bool diag = (ti == tj);
    int rq = lane >> 2, cq = (lane & 3)*2;
    #pragma unroll
    for (int i = 0; i < 4; i++){
        int lr0 = wm + i*16 + rq;
        #pragma unroll
        for (int j = 0; j < 4; j++){
            int lc = wn + j*8 + cq;
            float2 v0 = make_float2(c[i][j][0]*SCALE_LOG2E, c[i][j][1]*SCALE_LOG2E);
            float2 v1 = make_float2(c[i][j][2]*SCALE_LOG2E, c[i][j][3]*SCALE_LOG2E);
            if (diag){
                if (lr0 < lc)       v0.x = MASKVAL;
                if (lr0 < lc+1)     v0.y = MASKVAL;
                if (lr0+8 < lc)     v1.x = MASKVAL;
                if (lr0+8 < lc+1)   v1.y = MASKVAL;
            }
            size_t row0 = (size_t)(ti*128 + lr0);
            int col = tj*128 + lc;
            *(__half2*)&Cb[row0*NSEQ + col]     = __floats2half2_rn(v0.x, v0.y);
            *(__half2*)&Cb[(row0+8)*NSEQ + col] = __floats2half2_rn(v1.x, v1.y);
        }
    }
}

// ---------------- rowsum: compact 128x128 triangular tiles ----------------
template<int T>
__global__ void __launch_bounds__(256) rowsum_kernel()
{
    __shared__ float qcol[(T>0)?T:1][128];
    __shared__ float qrow[(T>0)?T:1][128];
    int b = blockIdx.y;
    int ti, tj; tri_decode_(blockIdx.x, ti, tj);
    int n0 = ti*128, m0 = tj*128;
    int tid = threadIdx.x;

    if (T > 0){
        for (int i = tid; i < 128*T; i += 256){
            int u = i >> 7, li = i & 127;
            qcol[u][li] = g_chpt[u][b*NSEQ + m0 + li];
            qrow[u][li] = g_chpt[u][b*NSEQ + n0 + li];
        }
        __syncthreads();
    }

    int lane = tid & 31, w = tid >> 5;
    const __half* Cb = g_C + (size_t)b*NSEQ*NSEQ;
    float4 q[(T>0)?T:1];
    #pragma unroll
    for (int u = 0; u < T; u++) q[u] = *(float4*)&qcol[u][lane*4];

    #pragma unroll
    for (int half = 0; half < 2; half++){
        int rbase = w*16 + half*8;
        float acc[8] = {0.f,0.f,0.f,0.f,0.f,0.f,0.f,0.f};
        #pragma unroll
        for (int r = 0; r < 8; r++){
            int n = n0 + rbase + r;
            float4 cc = ldC4_(&Cb[(size_t)n*NSEQ + m0 + lane*4]);
            float fx = 1.f, fy = 1.f, fz = 1.f, fw = 1.f;
            #pragma unroll
            for (int u = 0; u < T; u++){
                float cn = qrow[u][rbase+r];
                fx = fmaf(cn, q[u].x, fx);
                fy = fmaf(cn, q[u].y, fy);
                fz = fmaf(cn, q[u].z, fz);
                fw = fmaf(cn, q[u].w, fw);
            }
            float e0 = (T==0) ? ex2_(cc.x) : ex2_(cc.x*fx);
            float e1 = (T==0) ? ex2_(cc.y) : ex2_(cc.y*fy);
            float e2 = (T==0) ? ex2_(cc.z) : ex2_(cc.z*fz);
            float e3 = (T==0) ? ex2_(cc.w) : ex2_(cc.w*fw);
            acc[r] += (e0 + e1) + (e2 + e3);
        }
        #pragma unroll
        for (int r = 0; r < 8; r++){
            float s = acc[r];
            #pragma unroll
            for (int o = 16; o > 0; o >>= 1) s += __shfl_down_sync(0xffffffffu, s, o);
            if (lane == 0) atomicAdd(&g_rsT[T][b*NSEQ + n0 + rbase + r], s);
        }
    }
}

// ---------------- colsum: compact 128x128 triangular tiles ----------------
template<int T>
__global__ void __launch_bounds__(256) colsum_kernel()
{
    __shared__ float qcol[(T>0)?T:1][128];
    __shared__ float qrow[(T>0)?T:1][128];
    __shared__ float irsrow[128];
    int b = blockIdx.y;
    int ti, tj; tri_decode_(blockIdx.x, ti, tj);
    int n0 = ti*128, m0 = tj*128;
    int tid = threadIdx.x;

    if (tid < 128) irsrow[tid] = __frcp_rn(g_rsT[T][b*NSEQ + n0 + tid]);
    if (T > 0){
        for (int i = tid; i < 128*T; i += 256){
            int u = i >> 7, li = i & 127;
            qcol[u][li] = g_chpt[u][b*NSEQ + m0 + li];
            qrow[u][li] = g_chpt[u][b*NSEQ + n0 + li];
        }
    }
    __syncthreads();

    int lane = tid & 31, w = tid >> 5;
    int m = m0 + lane*4;
    const __half* Cb = g_C + (size_t)b*NSEQ*NSEQ;
    float4 q[(T>0)?T:1];
    #pragma unroll
    for (int u = 0; u < T; u++) q[u] = *(float4*)&qcol[u][lane*4];
    float4 acc = make_float4(0.f,0.f,0.f,0.f);
    #pragma unroll 4
    for (int r = 0; r < 16; r++){
        int rr = w*16 + r;
        int n = n0 + rr;
        float irs = irsrow[rr];
        float4 cc = ldC4_(&Cb[(size_t)n*NSEQ + m]);
        float fx = 1.f, fy = 1.f, fz = 1.f, fw = 1.f;
        #pragma unroll
        for (int u = 0; u < T; u++){
            float cn = qrow[u][rr];
            fx = fmaf(cn, q[u].x, fx);
            fy = fmaf(cn, q[u].y, fy);
            fz = fmaf(cn, q[u].z, fz);
            fw = fmaf(cn, q[u].w, fw);
        }
        acc.x += ((T==0) ? ex2_(cc.x) : ex2_(cc.x*fx))*irs;
        acc.y += ((T==0) ? ex2_(cc.y) : ex2_(cc.y*fy))*irs;
        acc.z += ((T==0) ? ex2_(cc.z) : ex2_(cc.z*fz))*irs;
        acc.w += ((T==0) ? ex2_(cc.w) : ex2_(cc.w*fw))*irs;
    }
    __shared__ float4 s4[256];
    s4[tid] = acc;
    __syncthreads();
    if (tid < 32){
        float4 t = s4[tid];
        #pragma unroll
        for (int r = 1; r < 8; r++){
            float4 o = s4[tid + r*32];
            t.x += o.x; t.y += o.y; t.z += o.z; t.w += o.w;
        }
        float* dst = &g_recv[b*NSEQ + m0 + tid*4];
        atomicAdd(dst+0, t.x);
        atomicAdd(dst+1, t.y);
        atomicAdd(dst+2, t.z);
        atomicAdd(dst+3, t.w);
    }
}

// ---------------- charge update + pack + re-zero recv ----------------
__global__ void chargeupd_kernel(int t, const float* __restrict__ cdp,
                                        const float* __restrict__ ssp)
{
    int i = blockIdx.x*256 + threadIdx.x;
    if (i >= BN) return;
    float cd = *cdp, ss = *ssp;
    float r  = g_recv[i];
    float ch = g_ch[i] * (1.f - cd*sigmoidf_(r - 1.f));
    g_ch[i] = ch;
    g_chpt[t][i] = sqrtf(ss)*ch;
    g_recv[i] = 0.f;
}

// ---------------- fused final: row-strip rowsum + normalized write ----------------
__global__ void __launch_bounds__(256) final_fused_kernel(float* __restrict__ out)
{
    __shared__ float P[NSEQ];
    __shared__ float red[9];
    int blk = blockIdx.x;
    int b = blk & 1;
    int n = (NSEQ-1) - (blk >> 1);           // long rows first
    const __half* Crow = g_C + ((size_t)b*NSEQ + n)*NSEQ;
    int tid = threadIdx.x, lane = tid & 31, wid = tid >> 5;
    int L = ((n >> 7) + 1) << 7;             // row length rounded up to 128 (masked tail ~ 0)
    float cn0 = g_chpt[0][b*NSEQ+n];
    float cn1 = g_chpt[1][b*NSEQ+n];
    float cn2 = g_chpt[2][b*NSEQ+n];
    float cn3 = g_chpt[3][b*NSEQ+n];
    float sum = 0.f;
    for (int i = tid; i < (L >> 2); i += 256){
        float4 cc = ldC4_(&Crow[i*4]);
        int m = b*NSEQ + i*4;
        float4 t0 = *(const float4*)&g_chpt[0][m];
        float4 t1 = *(const float4*)&g_chpt[1][m];
        float4 t2 = *(const float4*)&g_chpt[2][m];
        float4 t3 = *(const float4*)&g_chpt[3][m];
        float fx = fmaf(cn0,t0.x, fmaf(cn1,t1.x, fmaf(cn2,t2.x, fmaf(cn3,t3.x, 1.f))));
        float fy = fmaf(cn0,t0.y, fmaf(cn1,t1.y, fmaf(cn2,t2.y, fmaf(cn3,t3.y, 1.f))));
        float fz = fmaf(cn0,t0.z, fmaf(cn1,t1.z, fmaf(cn2,t2.z, fmaf(cn3,t3.z, 1.f))));
        float fw = fmaf(cn0,t0.w, fmaf(cn1,t1.w, fmaf(cn2,t2.w, fmaf(cn3,t3.w, 1.f))));
        float p0 = ex2_(cc.x*fx), p1 = ex2_(cc.y*fy);
        float p2 = ex2_(cc.z*fz), p3 = ex2_(cc.w*fw);
        *(float4*)&P[i*4] = make_float4(p0,p1,p2,p3);
        sum += (p0 + p1) + (p2 + p3);
    }
    #pragma unroll
    for (int o = 16; o > 0; o >>= 1) sum += __shfl_down_sync(0xffffffffu, sum, o);
    if (lane == 0) red[wid] = sum;
    __syncthreads();
    if (tid == 0){
        float s = 0.f;
        #pragma unroll
        for (int w = 0; w < 8; w++) s += red[w];
        red[8] = 1.f / s;
    }
    __syncthreads();
    float irs = red[8];
    float* orow = out + ((size_t)b*NSEQ + n)*NSEQ;
    int L4 = L >> 2;
    for (int i = tid; i < NSEQ/4; i += 256){
        float4 v = make_float4(0.f,0.f,0.f,0.f);
        if (i < L4){
            float4 p = *(float4*)&P[i*4];
            v = make_float4(p.x*irs, p.y*irs, p.z*irs, p.w*irs);
        }
        __stcs((float4*)&orow[i*4], v);
    }
}

// ---------------- launch ----------------
extern "C" void kernel_launch(void* const* d_in, const int* in_sizes, int n_in,
                              void* d_out, int out_size)
{
    const float* feat = (const float*)d_in[0];
    const float* cosb = (const float*)d_in[1];
    const float* sinb = (const float*)d_in[2];
    // d_in[3] = mask (causal; not needed)
    const float* Wq   = (const float*)d_in[4];
    const float* Wk   = (const float*)d_in[5];
    const float* cw   = (const float*)d_in[6];
    const float* cb   = (const float*)d_in[7];
    const float* ssp  = (const float*)d_in[8];
    const float* cdp  = (const float*)d_in[9];
    float* out = (float*)d_out;

    const int GSMEM = 4*128*SQ*2;   // 73728 bytes
    static int smem_set = 0;
    if (!smem_set){
        cudaFuncSetAttribute(gemm_mma_kernel, cudaFuncAttributeMaxDynamicSharedMemorySize, GSMEM);
        cudaFuncSetAttribute(qk_mma_kernel, cudaFuncAttributeMaxDynamicSharedMemorySize, QK_SMEM_B);
        smem_set = 1;
    }

    qk_mma_kernel<<<BN/64, 256, QK_SMEM_B>>>(feat, cosb, sinb, Wq, Wk);
    charge0_kernel<<<BN/8, 256>>>(feat, cw, cb);

    const int T = NSEQ/128;
    dim3 gtri(T*(T+1)/2, BATCH);
    gemm_mma_kernel<<<gtri, 256, GSMEM>>>();

    rowsum_kernel<0><<<gtri, 256>>>();
    colsum_kernel<0><<<gtri, 256>>>();
    chargeupd_kernel<<<BN/256, 256>>>(0, cdp, ssp);

    rowsum_kernel<1><<<gtri, 256>>>();
    colsum_kernel<1><<<gtri, 256>>>();
    chargeupd_kernel<<<BN/256, 256>>>(1, cdp, ssp);

    rowsum_kernel<2><<<gtri, 256>>>();
    colsum_kernel<2><<<gtri, 256>>>();
    chargeupd_kernel<<<BN/256, 256>>>(2, cdp, ssp);

    rowsum_kernel<3><<<gtri, 256>>>();
    colsum_kernel<3><<<gtri, 256>>>();
    chargeupd_kernel<<<BN/256, 256>>>(3, cdp, ssp);

    final_fused_kernel<<<BN, 256>>>(out);
}

// round 17
// speedup vs baseline: 2.7568x; 1.0076x over previous
#include <cuda_runtime.h>
#include <cuda_bf16.h>
#include <cuda_fp16.h>
#include <cstdint>
#include <math.h>

#define NSEQ 4096
#define BATCH 2
#define BN (BATCH*NSEQ)
#define FDIM 512
#define DDIM 64
#define MASKVAL (-30000.0f)
#define SCALE_LOG2E (0.125f*1.4426950408889634f)
#define SQ 72   // padded bf16 row stride for mma smem tiles

// ---------------- scratch (device globals; no allocation allowed) ----------------
__device__ float g_Q[(size_t)BN*DDIM];
__device__ float g_K[(size_t)BN*DDIM];
__device__ __half g_C[(size_t)BATCH*NSEQ*NSEQ]; // C' = (QK^T/8)*log2e fp16; above-diag of diag tiles = MASKVAL
__device__ float g_ch[BN];                       // current charge
__device__ float g_chpt[4][BN];                  // packed sqrt(ss)*charge history
__device__ float g_rsT[4][BN];                   // row sums per iteration
__device__ float g_recv[BN];                     // received accumulator (zeroed by chargeupd)

__device__ __forceinline__ float sigmoidf_(float x){ return 1.f/(1.f+__expf(-x)); }
__device__ __forceinline__ float ex2_(float x){ float y; asm("ex2.approx.f32 %0, %1;" : "=f"(y) : "f"(x)); return y; }
__device__ __forceinline__ uint32_t smem_u32_(const void* p){
    uint32_t a;
    asm("{ .reg .u64 t; cvta.to.shared.u64 t, %1; cvt.u32.u64 %0, t; }" : "=r"(a) : "l"(p));
    return a;
}
__device__ __forceinline__ void tri_decode_(int kidx, int& ti, int& tj){
    int t = (int)((sqrtf(8.f*(float)kidx + 1.f) - 1.f) * 0.5f);
    while ((t+1)*(t+2)/2 <= kidx) t++;
    while (t*(t+1)/2 > kidx) t--;
    ti = t; tj = kidx - t*(t+1)/2;
}
// load 4 consecutive fp16 C values as float4
__device__ __forceinline__ float4 ldC4_(const __half* p){
    uint2 u = __ldg((const uint2*)p);
    __half2 h01 = *reinterpret_cast<__half2*>(&u.x);
    __half2 h23 = *reinterpret_cast<__half2*>(&u.y);
    float2 a = __half22float2(h01);
    float2 b = __half22float2(h23);
    return make_float4(a.x, a.y, b.x, b.y);
}

// ---------------- Q/K projection via mma.sync bf16 hi/lo + in-register RoPE ----------------
#define QK_SMEM_B (27648*2)

__global__ void __launch_bounds__(256) qk_mma_kernel(const float* __restrict__ feat,
                                                     const float* __restrict__ cosb,
                                                     const float* __restrict__ sinb,
                                                     const float* __restrict__ Wq,
                                                     const float* __restrict__ Wk)
{
    extern __shared__ __nv_bfloat16 sm[];
    __nv_bfloat16* Ahi = sm;
    __nv_bfloat16* Alo = sm + 4608;
    int tid = threadIdx.x, lane = tid & 31, w = tid >> 5;
    long rowbase = (long)blockIdx.x*64;
    int isK = w >> 2;
    int wr0 = (w & 3)*16;
    float acc[8][4] = {};

    for (int f0 = 0; f0 < FDIM; f0 += 64){
        __syncthreads();
        for (int i = tid; i < 64*32; i += 256){
            int r = i >> 5, c2 = i & 31;
            float2 v = *(const float2*)&feat[(rowbase + r)*FDIM + f0 + c2*2];
            __nv_bfloat16 hx = __float2bfloat16_rn(v.x), hy = __float2bfloat16_rn(v.y);
            __nv_bfloat16 lx = __float2bfloat16_rn(v.x - __bfloat162float(hx));
            __nv_bfloat16 ly = __float2bfloat16_rn(v.y - __bfloat162float(hy));
            int o = r*SQ + c2*2;
            *(__nv_bfloat162*)&Ahi[o] = __nv_bfloat162(hx, hy);
            *(__nv_bfloat162*)&Alo[o] = __nv_bfloat162(lx, ly);
        }
        for (int i = tid; i < 64*32; i += 256){
            int f = i >> 5, c2 = i & 31;
            float2 q = *(const float2*)&Wq[(f0+f)*DDIM + c2*2];
            float2 k = *(const float2*)&Wk[(f0+f)*DDIM + c2*2];
            int o = f*SQ + c2*2;
            __nv_bfloat16 qhx = __float2bfloat16_rn(q.x), qhy = __float2bfloat16_rn(q.y);
            __nv_bfloat16 khx = __float2bfloat16_rn(k.x), khy = __float2bfloat16_rn(k.y);
            __nv_bfloat16 qlx = __float2bfloat16_rn(q.x - __bfloat162float(qhx));
            __nv_bfloat16 qly = __float2bfloat16_rn(q.y - __bfloat162float(qhy));
            __nv_bfloat16 klx = __float2bfloat16_rn(k.x - __bfloat162float(khx));
            __nv_bfloat16 kly = __float2bfloat16_rn(k.y - __bfloat162float(khy));
            *(__nv_bfloat162*)&sm[ 9216 + o] = __nv_bfloat162(qhx, qhy);
            *(__nv_bfloat162*)&sm[13824 + o] = __nv_bfloat162(qlx, qly);
            *(__nv_bfloat162*)&sm[18432 + o] = __nv_bfloat162(khx, khy);
            *(__nv_bfloat162*)&sm[23040 + o] = __nv_bfloat162(klx, kly);
        }
        __syncthreads();

        uint32_t a_hi = smem_u32_(Ahi), a_lo = smem_u32_(Alo);
        uint32_t b_hi = smem_u32_(sm + (isK ? 18432 : 9216));
        uint32_t b_lo = smem_u32_(sm + (isK ? 23040 : 13824));
        #pragma unroll
        for (int combo = 0; combo < 3; combo++){
            uint32_t abase = (combo == 2) ? a_lo : a_hi;
            uint32_t bbase = (combo == 1) ? b_lo : b_hi;
            #pragma unroll
            for (int k0 = 0; k0 < 64; k0 += 16){
                uint32_t a[4];
                uint32_t aaddr = abase + (uint32_t)(((wr0 + (lane & 15))*SQ + k0 + (lane >> 4)*8)*2);
                asm volatile("ldmatrix.sync.aligned.m8n8.x4.shared.b16 {%0,%1,%2,%3}, [%4];"
                    : "=r"(a[0]), "=r"(a[1]), "=r"(a[2]), "=r"(a[3]) : "r"(aaddr));
                #pragma unroll
                for (int j = 0; j < 8; j++){
                    uint32_t b0, b1;
                    uint32_t baddr = bbase + (uint32_t)(((k0 + (lane & 15))*SQ + j*8)*2);
                    asm volatile("ldmatrix.sync.aligned.m8n8.x2.trans.shared.b16 {%0,%1}, [%2];"
                        : "=r"(b0), "=r"(b1) : "r"(baddr));
                    asm volatile("mma.sync.aligned.m16n8k16.row.col.f32.bf16.bf16.f32 "
                        "{%0,%1,%2,%3}, {%4,%5,%6,%7}, {%8,%9}, {%0,%1,%2,%3};"
                        : "+f"(acc[j][0]), "+f"(acc[j][1]), "+f"(acc[j][2]), "+f"(acc[j][3])
                        : "r"(a[0]), "r"(a[1]), "r"(a[2]), "r"(a[3]), "r"(b0), "r"(b1));
                }
            }
        }
    }

    float* outp = isK ? g_K : g_Q;
    int rq = lane >> 2, cq = (lane & 3)*2;
    #pragma unroll
    for (int h = 0; h < 2; h++){
        long n_ = rowbase + wr0 + rq + 8*h;
        int nn = (int)(n_ & (NSEQ-1));
        #pragma unroll
        for (int j = 0; j < 8; j++){
            int d0 = j*8 + cq;
            float v0 = acc[j][2*h], v1 = acc[j][2*h+1];
            float r0, r1;
            if (j < 4){ r0 = -acc[j+4][2*h]; r1 = -acc[j+4][2*h+1]; }
            else      { r0 =  acc[j-4][2*h]; r1 =  acc[j-4][2*h+1]; }
            float2 cs = *(const float2*)&cosb[nn*DDIM + d0];
            float2 sn = *(const float2*)&sinb[nn*DDIM + d0];
            float2 o = make_float2(fmaf(v0, cs.x, r0*sn.x), fmaf(v1, cs.y, r1*sn.y));
            *(float2*)&outp[n_*DDIM + d0] = o;
        }
    }
}

// ---------------- initial charge + zero recv/rsT/chpt ----------------
__global__ void charge0_kernel(const float* __restrict__ feat,
                               const float* __restrict__ cw,
                               const float* __restrict__ cb)
{
    int warp = threadIdx.x >> 5, lane = threadIdx.x & 31;
    long n = (long)blockIdx.x*8 + warp;
    if (n >= BN) return;
    float sum = 0.f;
    for (int f = lane; f < FDIM; f += 32) sum = fmaf(feat[n*FDIM+f], cw[f], sum);
    #pragma unroll
    for (int o = 16; o > 0; o >>= 1) sum += __shfl_down_sync(0xffffffffu, sum, o);
    if (lane == 0){
        g_ch[n] = sigmoidf_(sum + cb[0]);
        g_recv[n] = 0.f;
        #pragma unroll
        for (int t = 0; t < 4; t++){ g_rsT[t][n] = 0.f; g_chpt[t][n] = 0.f; }
    }
}

// ---------------- gemm via mma.sync bf16 hi/lo: fp16 C', masked, FUSED rowsum<0> ----------------
__global__ void __launch_bounds__(256) gemm_mma_kernel()
{
    extern __shared__ __nv_bfloat16 smb[];
    __nv_bfloat16* Qhi = smb;
    __nv_bfloat16* Qlo = smb + 128*SQ;
    __nv_bfloat16* Khi = smb + 2*128*SQ;
    __nv_bfloat16* Klo = smb + 3*128*SQ;

    int b = blockIdx.y;
    int ti, tj; tri_decode_(blockIdx.x, ti, tj);

    const float* Qb = g_Q + ((long)b*NSEQ + (long)ti*128)*DDIM;
    const float* Kb = g_K + ((long)b*NSEQ + (long)tj*128)*DDIM;
    int tid = threadIdx.x;
    for (int i = tid; i < 128*32; i += 256){
        int r = i >> 5, c2 = i & 31;
        float2 q = *(const float2*)&Qb[r*64 + c2*2];
        float2 k = *(const float2*)&Kb[r*64 + c2*2];
        int o = r*SQ + c2*2;
        __nv_bfloat16 qhx = __float2bfloat16_rn(q.x), qhy = __float2bfloat16_rn(q.y);
        __nv_bfloat16 khx = __float2bfloat16_rn(k.x), khy = __float2bfloat16_rn(k.y);
        __nv_bfloat16 qlx = __float2bfloat16_rn(q.x - __bfloat162float(qhx));
        __nv_bfloat16 qly = __float2bfloat16_rn(q.y - __bfloat162float(qhy));
        __nv_bfloat16 klx = __float2bfloat16_rn(k.x - __bfloat162float(khx));
        __nv_bfloat16 kly = __float2bfloat16_rn(k.y - __bfloat162float(khy));
        *(__nv_bfloat162*)&Qhi[o] = __nv_bfloat162(qhx, qhy);
        *(__nv_bfloat162*)&Qlo[o] = __nv_bfloat162(qlx, qly);
        *(__nv_bfloat162*)&Khi[o] = __nv_bfloat162(khx, khy);
        *(__nv_bfloat162*)&Klo[o] = __nv_bfloat162(klx, kly);
    }
    __syncthreads();

    int lane = tid & 31, w = tid >> 5;
    int wm = (w & 1)*64, wn = (w >> 1)*32;

    float c[4][4][4] = {};

    uint32_t qhi_b = smem_u32_(Qhi), qlo_b = smem_u32_(Qlo);
    uint32_t khi_b = smem_u32_(Khi), klo_b = smem_u32_(Klo);

    int ar = lane & 15, ac8 = lane >> 4;
    int br = lane & 7,  bc8 = (lane >> 3) & 1;

    #pragma unroll
    for (int combo = 0; combo < 3; combo++){
        uint32_t abase = (combo == 2) ? qlo_b : qhi_b;
        uint32_t bbase = (combo == 1) ? klo_b : khi_b;
        #pragma unroll
        for (int k0 = 0; k0 < 64; k0 += 16){
            uint32_t a[4][4], bf[4][2];
            #pragma unroll
            for (int i = 0; i < 4; i++){
                uint32_t addr = abase + (uint32_t)(((wm + i*16 + ar)*SQ + k0 + ac8*8)*2);
                asm volatile("ldmatrix.sync.aligned.m8n8.x4.shared.b16 {%0,%1,%2,%3}, [%4];"
                    : "=r"(a[i][0]), "=r"(a[i][1]), "=r"(a[i][2]), "=r"(a[i][3]) : "r"(addr));
            }
            #pragma unroll
            for (int j = 0; j < 4; j++){
                uint32_t addr = bbase + (uint32_t)(((wn + j*8 + br)*SQ + k0 + bc8*8)*2);
                asm volatile("ldmatrix.sync.aligned.m8n8.x2.shared.b16 {%0,%1}, [%2];"
                    : "=r"(bf[j][0]), "=r"(bf[j][1]) : "r"(addr));
            }
            #pragma unroll
            for (int i = 0; i < 4; i++)
                #pragma unroll
                for (int j = 0; j < 4; j++)
                    asm volatile("mma.sync.aligned.m16n8k16.row.col.f32.bf16.bf16.f32 "
                        "{%0,%1,%2,%3}, {%4,%5,%6,%7}, {%8,%9}, {%0,%1,%2,%3};"
                        : "+f"(c[i][j][0]), "+f"(c[i][j][1]), "+f"(c[i][j][2]), "+f"(c[i][j][3])
                        : "r"(a[i][0]), "r"(a[i][1]), "r"(a[i][2]), "r"(a[i][3]),
                          "r"(bf[j][0]), "r"(bf[j][1]));
        }
    }

    // epilogue: scale, diag mask, fp16 store + fused rowsum<0> (exp2 of stored value)
    __half* Cb = g_C + (size_t)b*NSEQ*NSEQ;
    bool diag = (ti == tj);
    int rq = lane >> 2, cq = (lane & 3)*2;
    #pragma unroll
    for (int i = 0; i < 4; i++){
        int lr0 = wm + i*16 + rq;
        float rs0 = 0.f, rs1 = 0.f;     // row partials for rows lr0, lr0+8
        #pragma unroll
        for (int j = 0; j < 4; j++){
            int lc = wn + j*8 + cq;
            float2 v0 = make_float2(c[i][j][0]*SCALE_LOG2E, c[i][j][1]*SCALE_LOG2E);
            float2 v1 = make_float2(c[i][j][2]*SCALE_LOG2E, c[i][j][3]*SCALE_LOG2E);
            if (diag){
                if (lr0 < lc)       v0.x = MASKVAL;
                if (lr0 < lc+1)     v0.y = MASKVAL;
                if (lr0+8 < lc)     v1.x = MASKVAL;
                if (lr0+8 < lc+1)   v1.y = MASKVAL;
            }
            __half2 h0 = __floats2half2_rn(v0.x, v0.y);
            __half2 h1 = __floats2half2_rn(v1.x, v1.y);
            size_t row0 = (size_t)(ti*128 + lr0);
            int col = tj*128 + lc;
            *(__half2*)&Cb[row0*NSEQ + col]     = h0;
            *(__half2*)&Cb[(row0+8)*NSEQ + col] = h1;
            float2 f0 = __half22float2(h0);
            float2 f1 = __half22float2(h1);
            rs0 += ex2_(f0.x) + ex2_(f0.y);
            rs1 += ex2_(f1.x) + ex2_(f1.y);
        }
        // quad reduce (lanes rq*4 .. rq*4+3 hold the same rows)
        rs0 += __shfl_xor_sync(0xffffffffu, rs0, 1);
        rs0 += __shfl_xor_sync(0xffffffffu, rs0, 2);
        rs1 += __shfl_xor_sync(0xffffffffu, rs1, 1);
        rs1 += __shfl_xor_sync(0xffffffffu, rs1, 2);
        if ((lane & 3) == 0){
            atomicAdd(&g_rsT[0][b*NSEQ + ti*128 + lr0],     rs0);
            atomicAdd(&g_rsT[0][b*NSEQ + ti*128 + lr0 + 8], rs1);
        }
    }
}

// ---------------- rowsum: compact 128x128 triangular tiles ----------------
template<int T>
__global__ void __launch_bounds__(256) rowsum_kernel()
{
    __shared__ float qcol[(T>0)?T:1][128];
    __shared__ float qrow[(T>0)?T:1][128];
    int b = blockIdx.y;
    int ti, tj; tri_decode_(blockIdx.x, ti, tj);
    int n0 = ti*128, m0 = tj*128;
    int tid = threadIdx.x;

    if (T > 0){
        for (int i = tid; i < 128*T; i += 256){
            int u = i >> 7, li = i & 127;
            qcol[u][li] = g_chpt[u][b*NSEQ + m0 + li];
            qrow[u][li] = g_chpt[u][b*NSEQ + n0 + li];
        }
        __syncthreads();
    }

    int lane = tid & 31, w = tid >> 5;
    const __half* Cb = g_C + (size_t)b*NSEQ*NSEQ;
    float4 q[(T>0)?T:1];
    #pragma unroll
    for (int u = 0; u < T; u++) q[u] = *(float4*)&qcol[u][lane*4];

    #pragma unroll
    for (int half = 0; half < 2; half++){
        int rbase = w*16 + half*8;
        float acc[8] = {0.f,0.f,0.f,0.f,0.f,0.f,0.f,0.f};
        #pragma unroll
        for (int r = 0; r < 8; r++){
            int n = n0 + rbase + r;
            float4 cc = ldC4_(&Cb[(size_t)n*NSEQ + m0 + lane*4]);
            float fx = 1.f, fy = 1.f, fz = 1.f, fw = 1.f;
            #pragma unroll
            for (int u = 0; u < T; u++){
                float cn = qrow[u][rbase+r];
                fx = fmaf(cn, q[u].x, fx);
                fy = fmaf(cn, q[u].y, fy);
                fz = fmaf(cn, q[u].z, fz);
                fw = fmaf(cn, q[u].w, fw);
            }
            float e0 = (T==0) ? ex2_(cc.x) : ex2_(cc.x*fx);
            float e1 = (T==0) ? ex2_(cc.y) : ex2_(cc.y*fy);
            float e2 = (T==0) ? ex2_(cc.z) : ex2_(cc.z*fz);
            float e3 = (T==0) ? ex2_(cc.w) : ex2_(cc.w*fw);
            acc[r] += (e0 + e1) + (e2 + e3);
        }
        #pragma unroll
        for (int r = 0; r < 8; r++){
            float s = acc[r];
            #pragma unroll
            for (int o = 16; o > 0; o >>= 1) s += __shfl_down_sync(0xffffffffu, s, o);
            if (lane == 0) atomicAdd(&g_rsT[T][b*NSEQ + n0 + rbase + r], s);
        }
    }
}

// ---------------- colsum: compact 128x128 triangular tiles ----------------
template<int T>
__global__ void __launch_bounds__(256) colsum_kernel()
{
    __shared__ float qcol[(T>0)?T:1][128];
    __shared__ float qrow[(T>0)?T:1][128];
    __shared__ float irsrow[128];
    int b = blockIdx.y;
    int ti, tj; tri_decode_(blockIdx.x, ti, tj);
    int n0 = ti*128, m0 = tj*128;
    int tid = threadIdx.x;

    if (tid < 128) irsrow[tid] = __frcp_rn(g_rsT[T][b*NSEQ + n0 + tid]);
    if (T > 0){
        for (int i = tid; i < 128*T; i += 256){
            int u = i >> 7, li = i & 127;
            qcol[u][li] = g_chpt[u][b*NSEQ + m0 + li];
            qrow[u][li] = g_chpt[u][b*NSEQ + n0 + li];
        }
    }
    __syncthreads();

    int lane = tid & 31, w = tid >> 5;
    int m = m0 + lane*4;
    const __half* Cb = g_C + (size_t)b*NSEQ*NSEQ;
    float4 q[(T>0)?T:1];
    #pragma unroll
    for (int u = 0; u < T; u++) q[u] = *(float4*)&qcol[u][lane*4];
    float4 acc = make_float4(0.f,0.f,0.f,0.f);
    #pragma unroll 4
    for (int r = 0; r < 16; r++){
        int rr = w*16 + r;
        int n = n0 + rr;
        float irs = irsrow[rr];
        float4 cc = ldC4_(&Cb[(size_t)n*NSEQ + m]);
        float fx = 1.f, fy = 1.f, fz = 1.f, fw = 1.f;
        #pragma unroll
        for (int u = 0; u < T; u++){
            float cn = qrow[u][rr];
            fx = fmaf(cn, q[u].x, fx);
            fy = fmaf(cn, q[u].y, fy);
            fz = fmaf(cn, q[u].z, fz);
            fw = fmaf(cn, q[u].w, fw);
        }
        acc.x += ((T==0) ? ex2_(cc.x) : ex2_(cc.x*fx))*irs;
        acc.y += ((T==0) ? ex2_(cc.y) : ex2_(cc.y*fy))*irs;
        acc.z += ((T==0) ? ex2_(cc.z) : ex2_(cc.z*fz))*irs;
        acc.w += ((T==0) ? ex2_(cc.w) : ex2_(cc.w*fw))*irs;
    }
    __shared__ float4 s4[256];
    s4[tid] = acc;
    __syncthreads();
    if (tid < 32){
        float4 t = s4[tid];
        #pragma unroll
        for (int r = 1; r < 8; r++){
            float4 o = s4[tid + r*32];
            t.x += o.x; t.y += o.y; t.z += o.z; t.w += o.w;
        }
        float* dst = &g_recv[b*NSEQ + m0 + tid*4];
        atomicAdd(dst+0, t.x);
        atomicAdd(dst+1, t.y);
        atomicAdd(dst+2, t.z);
        atomicAdd(dst+3, t.w);
    }
}

// ---------------- charge update + pack + re-zero recv ----------------
__global__ void chargeupd_kernel(int t, const float* __restrict__ cdp,
                                        const float* __restrict__ ssp)
{
    int i = blockIdx.x*256 + threadIdx.x;
    if (i >= BN) return;
    float cd = *cdp, ss = *ssp;
    float r  = g_recv[i];
    float ch = g_ch[i] * (1.f - cd*sigmoidf_(r - 1.f));
    g_ch[i] = ch;
    g_chpt[t][i] = sqrtf(ss)*ch;
    g_recv[i] = 0.f;
}

// ---------------- fused final: row-strip rowsum + normalized write ----------------
__global__ void __launch_bounds__(256) final_fused_kernel(float* __restrict__ out)
{
    __shared__ float P[NSEQ];
    __shared__ float red[9];
    int blk = blockIdx.x;
    int b = blk & 1;
    int n = (NSEQ-1) - (blk >> 1);           // long rows first
    const __half* Crow = g_C + ((size_t)b*NSEQ + n)*NSEQ;
    int tid = threadIdx.x, lane = tid & 31, wid = tid >> 5;
    int L = ((n >> 7) + 1) << 7;             // row length rounded up to 128 (masked tail ~ 0)
    float cn0 = g_chpt[0][b*NSEQ+n];
    float cn1 = g_chpt[1][b*NSEQ+n];
    float cn2 = g_chpt[2][b*NSEQ+n];
    float cn3 = g_chpt[3][b*NSEQ+n];
    float sum = 0.f;
    for (int i = tid; i < (L >> 2); i += 256){
        float4 cc = ldC4_(&Crow[i*4]);
        int m = b*NSEQ + i*4;
        float4 t0 = *(const float4*)&g_chpt[0][m];
        float4 t1 = *(const float4*)&g_chpt[1][m];
        float4 t2 = *(const float4*)&g_chpt[2][m];
        float4 t3 = *(const float4*)&g_chpt[3][m];
        float fx = fmaf(cn0,t0.x, fmaf(cn1,t1.x, fmaf(cn2,t2.x, fmaf(cn3,t3.x, 1.f))));
        float fy = fmaf(cn0,t0.y, fmaf(cn1,t1.y, fmaf(cn2,t2.y, fmaf(cn3,t3.y, 1.f))));
        float fz = fmaf(cn0,t0.z, fmaf(cn1,t1.z, fmaf(cn2,t2.z, fmaf(cn3,t3.z, 1.f))));
        float fw = fmaf(cn0,t0.w, fmaf(cn1,t1.w, fmaf(cn2,t2.w, fmaf(cn3,t3.w, 1.f))));
        float p0 = ex2_(cc.x*fx), p1 = ex2_(cc.y*fy);
        float p2 = ex2_(cc.z*fz), p3 = ex2_(cc.w*fw);
        *(float4*)&P[i*4] = make_float4(p0,p1,p2,p3);
        sum += (p0 + p1) + (p2 + p3);
    }
    #pragma unroll
    for (int o = 16; o > 0; o >>= 1) sum += __shfl_down_sync(0xffffffffu, sum, o);
    if (lane == 0) red[wid] = sum;
    __syncthreads();
    if (tid == 0){
        float s = 0.f;
        #pragma unroll
        for (int w = 0; w < 8; w++) s += red[w];
        red[8] = 1.f / s;
    }
    __syncthreads();
    float irs = red[8];
    float* orow = out + ((size_t)b*NSEQ + n)*NSEQ;
    int L4 = L >> 2;
    for (int i = tid; i < NSEQ/4; i += 256){
        float4 v = make_float4(0.f,0.f,0.f,0.f);
        if (i < L4){
            float4 p = *(float4*)&P[i*4];
            v = make_float4(p.x*irs, p.y*irs, p.z*irs, p.w*irs);
        }
        __stcs((float4*)&orow[i*4], v);
    }
}

// ---------------- launch ----------------
extern "C" void kernel_launch(void* const* d_in, const int* in_sizes, int n_in,
                              void* d_out, int out_size)
{
    const float* feat = (const float*)d_in[0];
    const float* cosb = (const float*)d_in[1];
    const float* sinb = (const float*)d_in[2];
    // d_in[3] = mask (causal; not needed)
    const float* Wq   = (const float*)d_in[4];
    const float* Wk   = (const float*)d_in[5];
    const float* cw   = (const float*)d_in[6];
    const float* cb   = (const float*)d_in[7];
    const float* ssp  = (const float*)d_in[8];
    const float* cdp  = (const float*)d_in[9];
    float* out = (float*)d_out;

    const int GSMEM = 4*128*SQ*2;   // 73728 bytes
    static int smem_set = 0;
    if (!smem_set){
        cudaFuncSetAttribute(gemm_mma_kernel, cudaFuncAttributeMaxDynamicSharedMemorySize, GSMEM);
        cudaFuncSetAttribute(qk_mma_kernel, cudaFuncAttributeMaxDynamicSharedMemorySize, QK_SMEM_B);
        smem_set = 1;
    }

    qk_mma_kernel<<<BN/64, 256, QK_SMEM_B>>>(feat, cosb, sinb, Wq, Wk);
    charge0_kernel<<<BN/8, 256>>>(feat, cw, cb);

    const int T = NSEQ/128;
    dim3 gtri(T*(T+1)/2, BATCH);
    gemm_mma_kernel<<<gtri, 256, GSMEM>>>();   // includes fused rowsum<0>

    colsum_kernel<0><<<gtri, 256>>>();
    chargeupd_kernel<<<BN/256, 256>>>(0, cdp, ssp);

    rowsum_kernel<1><<<gtri, 256>>>();
    colsum_kernel<1><<<gtri, 256>>>();
    chargeupd_kernel<<<BN/256, 256>>>(1, cdp, ssp);

    rowsum_kernel<2><<<gtri, 256>>>();
    colsum_kernel<2><<<gtri, 256>>>();
    chargeupd_kernel<<<BN/256, 256>>>(2, cdp, ssp);

    rowsum_kernel<3><<<gtri, 256>>>();
    colsum_kernel<3><<<gtri, 256>>>();
    chargeupd_kernel<<<BN/256, 256>>>(3, cdp, ssp);

    final_fused_kernel<<<BN, 256>>>(out);
}